// round 1
// baseline (speedup 1.0000x reference)
#include <cuda_runtime.h>
#include <math.h>

#define L_      384
#define DE      128
#define DB      64
#define NH      4
#define DH      48
#define HD      (NH*DH)        // 192
#define NPAIR   (L_*L_)        // 147456
#define NK      (L_*DH)        // 18432
#define EPS_    1e-5f
#define INF_    1000000.0f
#define SCALE_  0.14433756729740643f   // 1/sqrt(48)

// ---------------- scratch (static device globals; no runtime allocation) ----------------
__device__ float g_eln [NPAIR*DE];      // [r=n*L+i][c]   LN(edge^T)
__device__ float g_qT  [NH*L_*DH*L_];   // [h][n][d][i]   K-major for logits GEMM
__device__ float g_kT  [NH*L_*DH*L_];   // [h][n][d][j]
__device__ float g_v   [L_*NH*L_*DH];   // [n][h][j][d]
__device__ float g_gate[NPAIR*HD];      // [r][h*DH+d]
__device__ float g_bh  [NH*L_*L_];      // [h][i][j]
__device__ float g_attn[NH*L_*L_];      // logits -> attn (in place)
__device__ float g_og  [NPAIR*HD];      // gated AV output, rows r=n*L+i

// ---------------- A: layernorm of transposed edge ----------------
__global__ void kA(const float* __restrict__ edge, const float* __restrict__ gg,
                   const float* __restrict__ bb) {
    int row  = blockIdx.x * 8 + threadIdx.y;          // r = n*L + i
    int n    = row / L_;
    int i    = row - n * L_;
    int lane = threadIdx.x;
    const float* x = edge + ((size_t)i * L_ + n) * DE;   // transpose: e[n][i] = edge[i][n]
    float v[4], s = 0.f, s2 = 0.f;
#pragma unroll
    for (int t = 0; t < 4; t++) {
        float xv = x[lane + 32*t];
        v[t] = xv; s += xv; s2 += xv*xv;
    }
#pragma unroll
    for (int o = 16; o; o >>= 1) {
        s  += __shfl_xor_sync(0xffffffffu, s,  o);
        s2 += __shfl_xor_sync(0xffffffffu, s2, o);
    }
    float mu = s * (1.f/DE);
    float var = s2 * (1.f/DE) - mu*mu;
    float r = rsqrtf(var + EPS_);
    float* y = g_eln + (size_t)row * DE;
#pragma unroll
    for (int t = 0; t < 4; t++) {
        int c = lane + 32*t;
        y[c] = (v[t]-mu)*r*gg[c] + bb[c];
    }
}

// ---------------- B: layernorm of transposed bias + Wb projection -> b_h[h][i][j] ----------------
__global__ void kB(const float* __restrict__ bias, const float* __restrict__ gg,
                   const float* __restrict__ bb, const float* __restrict__ Wb) {
    int p = blockIdx.x * 8 + threadIdx.y;             // p = i*L + j
    int i = p / L_;
    int j = p - i * L_;
    int lane = threadIdx.x;
    const float* x = bias + ((size_t)j * L_ + i) * DB;   // bi[i][j] = bias[j][i]
    float x0 = x[lane], x1 = x[lane+32];
    float s = x0 + x1, s2 = x0*x0 + x1*x1;
#pragma unroll
    for (int o = 16; o; o >>= 1) {
        s  += __shfl_xor_sync(0xffffffffu, s,  o);
        s2 += __shfl_xor_sync(0xffffffffu, s2, o);
    }
    float mu = s * (1.f/DB);
    float var = s2 * (1.f/DB) - mu*mu;
    float r = rsqrtf(var + EPS_);
    float y0 = (x0-mu)*r*gg[lane]    + bb[lane];
    float y1 = (x1-mu)*r*gg[lane+32] + bb[lane+32];
    float a[4];
#pragma unroll
    for (int h = 0; h < 4; h++)
        a[h] = y0 * Wb[lane*NH + h] + y1 * Wb[(lane+32)*NH + h];
#pragma unroll
    for (int h = 0; h < 4; h++)
#pragma unroll
        for (int o = 16; o; o >>= 1)
            a[h] += __shfl_xor_sync(0xffffffffu, a[h], o);
    if (lane < 4)
        g_bh[((size_t)lane * L_ + i) * L_ + j] = a[lane];
}

// ---------------- C: QKVG projections, [147456,128] @ [128,192], per-mode epilogues ----------------
__global__ void kC(const float* __restrict__ Wq, const float* __restrict__ Wk,
                   const float* __restrict__ Wv, const float* __restrict__ Wg,
                   const float* __restrict__ bg) {
    int mode = blockIdx.z;
    const float* W = (mode == 0) ? Wq : (mode == 1) ? Wk : (mode == 2) ? Wv : Wg;
    int r0 = blockIdx.x * 64, c0 = blockIdx.y * 64;
    __shared__ float As[64][65];   // [k][m]
    __shared__ float Bs[64][64];   // [k][n]
    int tx = threadIdx.x, ty = threadIdx.y, tid = ty*16 + tx;
    float acc[4][4] = {};
    for (int kt = 0; kt < 2; kt++) {
        int k0 = kt * 64;
        for (int e = tid; e < 4096; e += 256) {
            int m = e >> 6, kk = e & 63;
            As[kk][m] = g_eln[(size_t)(r0+m)*DE + k0 + kk];
        }
        for (int e = tid; e < 4096; e += 256) {
            int kk = e >> 6, cn = e & 63;
            Bs[kk][cn] = W[(size_t)(k0+kk)*HD + c0 + cn];
        }
        __syncthreads();
#pragma unroll
        for (int kk = 0; kk < 64; kk++) {
            float4 b4 = *(const float4*)&Bs[kk][tx*4];
            float a;
            a = As[kk][ty*4+0]; acc[0][0]+=a*b4.x; acc[0][1]+=a*b4.y; acc[0][2]+=a*b4.z; acc[0][3]+=a*b4.w;
            a = As[kk][ty*4+1]; acc[1][0]+=a*b4.x; acc[1][1]+=a*b4.y; acc[1][2]+=a*b4.z; acc[1][3]+=a*b4.w;
            a = As[kk][ty*4+2]; acc[2][0]+=a*b4.x; acc[2][1]+=a*b4.y; acc[2][2]+=a*b4.z; acc[2][3]+=a*b4.w;
            a = As[kk][ty*4+3]; acc[3][0]+=a*b4.x; acc[3][1]+=a*b4.y; acc[3][2]+=a*b4.z; acc[3][3]+=a*b4.w;
        }
        __syncthreads();
    }
    int n = r0 / L_;               // 64 | 384, so the whole tile shares n
    int ibase = r0 - n * L_;
#pragma unroll
    for (int mi = 0; mi < 4; mi++) {
        int r = r0 + ty*4 + mi;
        int i = ibase + ty*4 + mi;
#pragma unroll
        for (int ni = 0; ni < 4; ni++) {
            int c = c0 + tx*4 + ni;
            float val = acc[mi][ni];
            if (mode == 0) {
                int h = c / DH, d = c - h*DH;
                g_qT[(((size_t)h*L_ + n)*DH + d)*L_ + i] = val;
            } else if (mode == 1) {
                int h = c / DH, d = c - h*DH;
                g_kT[(((size_t)h*L_ + n)*DH + d)*L_ + i] = val;
            } else if (mode == 2) {
                int h = c / DH, d = c - h*DH;
                g_v[(((size_t)n*NH + h)*L_ + i)*DH + d] = val;
            } else {
                g_gate[(size_t)r*HD + c] = 1.f / (1.f + expf(-(val + bg[c])));
            }
        }
    }
}

// ---------------- C2: RoPE (in place on qT/kT) + q*SCALE, k/L ----------------
__global__ void kC2(const int* __restrict__ pos) {
    int t = blockIdx.x * 256 + threadIdx.x;
    int i = t % L_;    int rest = t / L_;
    int d = rest % 24; rest /= 24;
    int n = rest % L_; rest /= L_;
    int h = rest % NH;
    int side = rest / NH;                         // 0=q, 1=k
    float* P = side ? g_kT : g_qT;
    size_t base = (((size_t)h*L_ + n)*DH)*L_ + i;
    float x1 = P[base + (size_t)d*L_];
    float x2 = P[base + (size_t)(d+24)*L_];
    float p = (float)pos[i];
    float invf = powf(10000.f, -(float)d * (1.f/24.f));
    float ang = p * invf;
    float sn, cs;
    sincosf(ang, &sn, &cs);
    float sc = side ? (1.f/(float)L_) : SCALE_;
    P[base + (size_t)d*L_]      = (x1*cs - x2*sn) * sc;
    P[base + (size_t)(d+24)*L_] = (x1*sn + x2*cs) * sc;
}

// ---------------- D: logits GEMM per head, K=18432, + bias add ----------------
__global__ void kD() {
    int h  = blockIdx.z;
    int i0 = blockIdx.y * 64, j0 = blockIdx.x * 64;
    const float* A = g_qT + (size_t)h * NK * L_;   // [k][i]
    const float* B = g_kT + (size_t)h * NK * L_;   // [k][j]
    __shared__ float As[32][64];
    __shared__ float Bs[32][64];
    int tx = threadIdx.x, ty = threadIdx.y, tid = ty*16 + tx;
    float acc[4][4] = {};
    for (int kt = 0; kt < NK/32; kt++) {
        for (int e = tid; e < 2048; e += 256) {
            int kk = e >> 6, m = e & 63;
            As[kk][m] = A[(size_t)(kt*32 + kk)*L_ + i0 + m];
            Bs[kk][m] = B[(size_t)(kt*32 + kk)*L_ + j0 + m];
        }
        __syncthreads();
#pragma unroll
        for (int kk = 0; kk < 32; kk++) {
            float4 a4 = *(const float4*)&As[kk][ty*4];
            float4 b4 = *(const float4*)&Bs[kk][tx*4];
            acc[0][0]+=a4.x*b4.x; acc[0][1]+=a4.x*b4.y; acc[0][2]+=a4.x*b4.z; acc[0][3]+=a4.x*b4.w;
            acc[1][0]+=a4.y*b4.x; acc[1][1]+=a4.y*b4.y; acc[1][2]+=a4.y*b4.z; acc[1][3]+=a4.y*b4.w;
            acc[2][0]+=a4.z*b4.x; acc[2][1]+=a4.z*b4.y; acc[2][2]+=a4.z*b4.z; acc[2][3]+=a4.z*b4.w;
            acc[3][0]+=a4.w*b4.x; acc[3][1]+=a4.w*b4.y; acc[3][2]+=a4.w*b4.z; acc[3][3]+=a4.w*b4.w;
        }
        __syncthreads();
    }
#pragma unroll
    for (int mi = 0; mi < 4; mi++)
#pragma unroll
        for (int ni = 0; ni < 4; ni++) {
            size_t idx = ((size_t)h*L_ + i0 + ty*4 + mi)*L_ + j0 + tx*4 + ni;
            g_attn[idx] = acc[mi][ni] + g_bh[idx];
        }
}

// ---------------- E: softmax over j + post-softmax additive mask ----------------
__global__ void kE(const float* __restrict__ mask) {
    int b = blockIdx.x;               // b = h*L + i
    int h = b / L_;  (void)h;
    int i = b - (b / L_) * L_;
    float* row = g_attn + (size_t)b * L_;
    int t = threadIdx.x;              // 128 threads
    float v[3];
    float mx = -1e30f;
#pragma unroll
    for (int u = 0; u < 3; u++) { v[u] = row[t + 128*u]; mx = fmaxf(mx, v[u]); }
    __shared__ float sm[4], ssum[4];
#pragma unroll
    for (int o = 16; o; o >>= 1) mx = fmaxf(mx, __shfl_xor_sync(0xffffffffu, mx, o));
    if ((t & 31) == 0) sm[t >> 5] = mx;
    __syncthreads();
    mx = fmaxf(fmaxf(sm[0], sm[1]), fmaxf(sm[2], sm[3]));
    float s = 0.f;
#pragma unroll
    for (int u = 0; u < 3; u++) { v[u] = expf(v[u] - mx); s += v[u]; }
#pragma unroll
    for (int o = 16; o; o >>= 1) s += __shfl_xor_sync(0xffffffffu, s, o);
    if ((t & 31) == 0) ssum[t >> 5] = s;
    __syncthreads();
    s = ssum[0] + ssum[1] + ssum[2] + ssum[3];
    float inv = 1.f / s;
#pragma unroll
    for (int u = 0; u < 3; u++) {
        int j = t + 128*u;
        row[j] = v[u]*inv + INF_ * (mask[(size_t)i*L_ + j] - 1.f);
    }
}

// ---------------- F: out = attn @ v per (n,h), gated ----------------
__global__ void kF() {
    int h = blockIdx.z, n = blockIdx.y, i0 = blockIdx.x * 64;
    const float* A = g_attn + (size_t)h * L_ * L_;              // [i][j]
    const float* V = g_v + ((size_t)n*NH + h) * L_ * DH;        // [j][d]
    __shared__ float As[64][33];
    __shared__ float Vs[32][48];
    int tx = threadIdx.x /*0..11 -> d*/, ty = threadIdx.y /*0..15 -> i*/;
    int tid = ty*12 + tx;
    float acc[4][4] = {};
    for (int jt = 0; jt < 12; jt++) {
        for (int e = tid; e < 2048; e += 192) {
            int ii = e >> 5, jj = e & 31;
            As[ii][jj] = A[(size_t)(i0+ii)*L_ + jt*32 + jj];
        }
        for (int e = tid; e < 1536; e += 192) {
            int jj = e / 48, d = e - jj*48;
            Vs[jj][d] = V[(size_t)(jt*32 + jj)*DH + d];
        }
        __syncthreads();
#pragma unroll
        for (int jj = 0; jj < 32; jj++) {
            float4 v4 = *(const float4*)&Vs[jj][tx*4];
            float a;
            a = As[ty*4+0][jj]; acc[0][0]+=a*v4.x; acc[0][1]+=a*v4.y; acc[0][2]+=a*v4.z; acc[0][3]+=a*v4.w;
            a = As[ty*4+1][jj]; acc[1][0]+=a*v4.x; acc[1][1]+=a*v4.y; acc[1][2]+=a*v4.z; acc[1][3]+=a*v4.w;
            a = As[ty*4+2][jj]; acc[2][0]+=a*v4.x; acc[2][1]+=a*v4.y; acc[2][2]+=a*v4.z; acc[2][3]+=a*v4.w;
            a = As[ty*4+3][jj]; acc[3][0]+=a*v4.x; acc[3][1]+=a*v4.y; acc[3][2]+=a*v4.z; acc[3][3]+=a*v4.w;
        }
        __syncthreads();
    }
#pragma unroll
    for (int mi = 0; mi < 4; mi++) {
        int r = n*L_ + i0 + ty*4 + mi;
#pragma unroll
        for (int ni = 0; ni < 4; ni++) {
            int c = h*DH + tx*4 + ni;
            g_og[(size_t)r*HD + c] = acc[mi][ni] * g_gate[(size_t)r*HD + c];
        }
    }
}

// ---------------- G: final projection [147456,192]@[192,128] + output transpose ----------------
__global__ void kG(const float* __restrict__ Wo, float* __restrict__ out) {
    int r0 = blockIdx.x * 64, c0 = blockIdx.y * 64;
    __shared__ float As[64][65];   // [k][m]
    __shared__ float Bs[64][64];   // [k][n]
    int tx = threadIdx.x, ty = threadIdx.y, tid = ty*16 + tx;
    float acc[4][4] = {};
    for (int kt = 0; kt < 3; kt++) {
        int k0 = kt * 64;
        for (int e = tid; e < 4096; e += 256) {
            int m = e >> 6, kk = e & 63;
            As[kk][m] = g_og[(size_t)(r0+m)*HD + k0 + kk];
        }
        for (int e = tid; e < 4096; e += 256) {
            int kk = e >> 6, cn = e & 63;
            Bs[kk][cn] = Wo[(size_t)(k0+kk)*DE + c0 + cn];
        }
        __syncthreads();
#pragma unroll
        for (int kk = 0; kk < 64; kk++) {
            float4 b4 = *(const float4*)&Bs[kk][tx*4];
            float a;
            a = As[kk][ty*4+0]; acc[0][0]+=a*b4.x; acc[0][1]+=a*b4.y; acc[0][2]+=a*b4.z; acc[0][3]+=a*b4.w;
            a = As[kk][ty*4+1]; acc[1][0]+=a*b4.x; acc[1][1]+=a*b4.y; acc[1][2]+=a*b4.z; acc[1][3]+=a*b4.w;
            a = As[kk][ty*4+2]; acc[2][0]+=a*b4.x; acc[2][1]+=a*b4.y; acc[2][2]+=a*b4.z; acc[2][3]+=a*b4.w;
            a = As[kk][ty*4+3]; acc[3][0]+=a*b4.x; acc[3][1]+=a*b4.y; acc[3][2]+=a*b4.z; acc[3][3]+=a*b4.w;
        }
        __syncthreads();
    }
    int n = r0 / L_;
    int ibase = r0 - n * L_;
#pragma unroll
    for (int mi = 0; mi < 4; mi++) {
        int i = ibase + ty*4 + mi;
#pragma unroll
        for (int ni = 0; ni < 4; ni++) {
            out[((size_t)i*L_ + n)*DE + c0 + tx*4 + ni] = acc[mi][ni];   // undo row permute
        }
    }
}

// ---------------- launch ----------------
extern "C" void kernel_launch(void* const* d_in, const int* in_sizes, int n_in,
                              void* d_out, int out_size) {
    const float* edge  = (const float*)d_in[0];
    const float* bias  = (const float*)d_in[1];
    const int*   epos  = (const int*)  d_in[2];
    const float* emask = (const float*)d_in[3];
    const float* lneg  = (const float*)d_in[4];
    const float* lneb  = (const float*)d_in[5];
    const float* lnbg  = (const float*)d_in[6];
    const float* lnbb  = (const float*)d_in[7];
    const float* Wq    = (const float*)d_in[8];
    const float* Wk    = (const float*)d_in[9];
    const float* Wv    = (const float*)d_in[10];
    const float* Wb    = (const float*)d_in[11];
    const float* Wg    = (const float*)d_in[12];
    const float* bg    = (const float*)d_in[13];
    const float* Wo    = (const float*)d_in[14];
    float* out = (float*)d_out;

    dim3 b32x8(32, 8);
    kA<<<NPAIR/8, b32x8>>>(edge, lneg, lneb);
    kB<<<NPAIR/8, b32x8>>>(bias, lnbg, lnbb, Wb);
    kC<<<dim3(NPAIR/64, 3, 4), dim3(16,16)>>>(Wq, Wk, Wv, Wg, bg);
    kC2<<<(2*NH*L_*24*L_)/256, 256>>>(epos);
    kD<<<dim3(6, 6, NH), dim3(16,16)>>>();
    kE<<<NH*L_, 128>>>(emask);
    kF<<<dim3(6, L_, NH), dim3(12,16)>>>();
    kG<<<dim3(NPAIR/64, 2), dim3(16,16)>>>(Wo, out);
}

// round 2
// speedup vs baseline: 1.0004x; 1.0004x over previous
#include <cuda_runtime.h>
#include <math.h>

#define L_      384
#define DE      128
#define DB      64
#define NH      4
#define DH      48
#define HD      (NH*DH)        // 192
#define NPAIR   (L_*L_)        // 147456
#define NK      (L_*DH)        // 18432
#define EPS_    1e-5f
#define INF_    1000000.0f
#define SCALE_  0.14433756729740643f   // 1/sqrt(48)

// ---------------- scratch (static device globals; no runtime allocation) ----------------
__device__ float g_eln [NPAIR*DE];      // [r=n*L+i][c]   LN(edge^T)
__device__ float g_qT  [NH*L_*DH*L_];   // [h][n][d][i]   K-major for logits GEMM
__device__ float g_kT  [NH*L_*DH*L_];   // [h][n][d][j]
__device__ float g_v   [L_*NH*L_*DH];   // [n][h][j][d]
__device__ float g_gate[NPAIR*HD];      // [r][h*DH+d]
__device__ float g_bh  [NH*L_*L_];      // [h][i][j]
__device__ float g_attn[NH*L_*L_];      // logits -> attn (in place)
__device__ float g_og  [NPAIR*HD];      // gated AV output, rows r=n*L+i

// ---------------- A: layernorm of transposed edge ----------------
__global__ void kA(const float* __restrict__ edge, const float* __restrict__ gg,
                   const float* __restrict__ bb) {
    int row  = blockIdx.x * 8 + threadIdx.y;          // r = n*L + i
    int n    = row / L_;
    int i    = row - n * L_;
    int lane = threadIdx.x;
    const float* x = edge + ((size_t)i * L_ + n) * DE;   // transpose: e[n][i] = edge[i][n]
    float v[4], s = 0.f, s2 = 0.f;
#pragma unroll
    for (int t = 0; t < 4; t++) {
        float xv = x[lane + 32*t];
        v[t] = xv; s += xv; s2 += xv*xv;
    }
#pragma unroll
    for (int o = 16; o; o >>= 1) {
        s  += __shfl_xor_sync(0xffffffffu, s,  o);
        s2 += __shfl_xor_sync(0xffffffffu, s2, o);
    }
    float mu = s * (1.f/DE);
    float var = s2 * (1.f/DE) - mu*mu;
    float r = rsqrtf(var + EPS_);
    float* y = g_eln + (size_t)row * DE;
#pragma unroll
    for (int t = 0; t < 4; t++) {
        int c = lane + 32*t;
        y[c] = (v[t]-mu)*r*gg[c] + bb[c];
    }
}

// ---------------- B: layernorm of transposed bias + Wb projection -> b_h[h][i][j] ----------------
__global__ void kB(const float* __restrict__ bias, const float* __restrict__ gg,
                   const float* __restrict__ bb, const float* __restrict__ Wb) {
    int p = blockIdx.x * 8 + threadIdx.y;             // p = i*L + j
    int i = p / L_;
    int j = p - i * L_;
    int lane = threadIdx.x;
    const float* x = bias + ((size_t)j * L_ + i) * DB;   // bi[i][j] = bias[j][i]
    float x0 = x[lane], x1 = x[lane+32];
    float s = x0 + x1, s2 = x0*x0 + x1*x1;
#pragma unroll
    for (int o = 16; o; o >>= 1) {
        s  += __shfl_xor_sync(0xffffffffu, s,  o);
        s2 += __shfl_xor_sync(0xffffffffu, s2, o);
    }
    float mu = s * (1.f/DB);
    float var = s2 * (1.f/DB) - mu*mu;
    float r = rsqrtf(var + EPS_);
    float y0 = (x0-mu)*r*gg[lane]    + bb[lane];
    float y1 = (x1-mu)*r*gg[lane+32] + bb[lane+32];
    float a[4];
#pragma unroll
    for (int h = 0; h < 4; h++)
        a[h] = y0 * Wb[lane*NH + h] + y1 * Wb[(lane+32)*NH + h];
#pragma unroll
    for (int h = 0; h < 4; h++)
#pragma unroll
        for (int o = 16; o; o >>= 1)
            a[h] += __shfl_xor_sync(0xffffffffu, a[h], o);
    if (lane < 4)
        g_bh[((size_t)lane * L_ + i) * L_ + j] = a[lane];
}

// ---------------- C: QKVG projections, [147456,128] @ [128,192], per-mode epilogues ----------------
__global__ void kC(const float* __restrict__ Wq, const float* __restrict__ Wk,
                   const float* __restrict__ Wv, const float* __restrict__ Wg,
                   const float* __restrict__ bg) {
    int mode = blockIdx.z;
    const float* W = (mode == 0) ? Wq : (mode == 1) ? Wk : (mode == 2) ? Wv : Wg;
    int r0 = blockIdx.x * 64, c0 = blockIdx.y * 64;
    __shared__ float As[64][65];   // [k][m]
    __shared__ float Bs[64][64];   // [k][n]
    int tx = threadIdx.x, ty = threadIdx.y, tid = ty*16 + tx;
    float acc[4][4] = {};
    for (int kt = 0; kt < 2; kt++) {
        int k0 = kt * 64;
        for (int e = tid; e < 4096; e += 256) {
            int m = e >> 6, kk = e & 63;
            As[kk][m] = g_eln[(size_t)(r0+m)*DE + k0 + kk];
        }
        for (int e = tid; e < 4096; e += 256) {
            int kk = e >> 6, cn = e & 63;
            Bs[kk][cn] = W[(size_t)(k0+kk)*HD + c0 + cn];
        }
        __syncthreads();
#pragma unroll
        for (int kk = 0; kk < 64; kk++) {
            float4 b4 = *(const float4*)&Bs[kk][tx*4];
            float a;
            a = As[kk][ty*4+0]; acc[0][0]+=a*b4.x; acc[0][1]+=a*b4.y; acc[0][2]+=a*b4.z; acc[0][3]+=a*b4.w;
            a = As[kk][ty*4+1]; acc[1][0]+=a*b4.x; acc[1][1]+=a*b4.y; acc[1][2]+=a*b4.z; acc[1][3]+=a*b4.w;
            a = As[kk][ty*4+2]; acc[2][0]+=a*b4.x; acc[2][1]+=a*b4.y; acc[2][2]+=a*b4.z; acc[2][3]+=a*b4.w;
            a = As[kk][ty*4+3]; acc[3][0]+=a*b4.x; acc[3][1]+=a*b4.y; acc[3][2]+=a*b4.z; acc[3][3]+=a*b4.w;
        }
        __syncthreads();
    }
    int n = r0 / L_;               // 64 | 384, so the whole tile shares n
    int ibase = r0 - n * L_;
#pragma unroll
    for (int mi = 0; mi < 4; mi++) {
        int r = r0 + ty*4 + mi;
        int i = ibase + ty*4 + mi;
#pragma unroll
        for (int ni = 0; ni < 4; ni++) {
            int c = c0 + tx*4 + ni;
            float val = acc[mi][ni];
            if (mode == 0) {
                int h = c / DH, d = c - h*DH;
                g_qT[(((size_t)h*L_ + n)*DH + d)*L_ + i] = val;
            } else if (mode == 1) {
                int h = c / DH, d = c - h*DH;
                g_kT[(((size_t)h*L_ + n)*DH + d)*L_ + i] = val;
            } else if (mode == 2) {
                int h = c / DH, d = c - h*DH;
                g_v[(((size_t)n*NH + h)*L_ + i)*DH + d] = val;
            } else {
                g_gate[(size_t)r*HD + c] = 1.f / (1.f + expf(-(val + bg[c])));
            }
        }
    }
}

// ---------------- C2: RoPE (in place on qT/kT) + q*SCALE, k/L ----------------
__global__ void kC2(const int* __restrict__ pos) {
    int t = blockIdx.x * 256 + threadIdx.x;
    int i = t % L_;    int rest = t / L_;
    int d = rest % 24; rest /= 24;
    int n = rest % L_; rest /= L_;
    int h = rest % NH;
    int side = rest / NH;                         // 0=q, 1=k
    float* P = side ? g_kT : g_qT;
    size_t base = (((size_t)h*L_ + n)*DH)*L_ + i;
    float x1 = P[base + (size_t)d*L_];
    float x2 = P[base + (size_t)(d+24)*L_];
    float p = (float)pos[i];
    float invf = powf(10000.f, -(float)d * (1.f/24.f));
    float ang = p * invf;
    float sn, cs;
    sincosf(ang, &sn, &cs);
    float sc = side ? (1.f/(float)L_) : SCALE_;
    P[base + (size_t)d*L_]      = (x1*cs - x2*sn) * sc;
    P[base + (size_t)(d+24)*L_] = (x1*sn + x2*cs) * sc;
}

// ---------------- D: logits GEMM per head, K=18432, + bias add ----------------
__global__ void kD() {
    int h  = blockIdx.z;
    int i0 = blockIdx.y * 64, j0 = blockIdx.x * 64;
    const float* A = g_qT + (size_t)h * NK * L_;   // [k][i]
    const float* B = g_kT + (size_t)h * NK * L_;   // [k][j]
    __shared__ float As[32][64];
    __shared__ float Bs[32][64];
    int tx = threadIdx.x, ty = threadIdx.y, tid = ty*16 + tx;
    float acc[4][4] = {};
    for (int kt = 0; kt < NK/32; kt++) {
        for (int e = tid; e < 2048; e += 256) {
            int kk = e >> 6, m = e & 63;
            As[kk][m] = A[(size_t)(kt*32 + kk)*L_ + i0 + m];
            Bs[kk][m] = B[(size_t)(kt*32 + kk)*L_ + j0 + m];
        }
        __syncthreads();
#pragma unroll
        for (int kk = 0; kk < 32; kk++) {
            float4 a4 = *(const float4*)&As[kk][ty*4];
            float4 b4 = *(const float4*)&Bs[kk][tx*4];
            acc[0][0]+=a4.x*b4.x; acc[0][1]+=a4.x*b4.y; acc[0][2]+=a4.x*b4.z; acc[0][3]+=a4.x*b4.w;
            acc[1][0]+=a4.y*b4.x; acc[1][1]+=a4.y*b4.y; acc[1][2]+=a4.y*b4.z; acc[1][3]+=a4.y*b4.w;
            acc[2][0]+=a4.z*b4.x; acc[2][1]+=a4.z*b4.y; acc[2][2]+=a4.z*b4.z; acc[2][3]+=a4.z*b4.w;
            acc[3][0]+=a4.w*b4.x; acc[3][1]+=a4.w*b4.y; acc[3][2]+=a4.w*b4.z; acc[3][3]+=a4.w*b4.w;
        }
        __syncthreads();
    }
#pragma unroll
    for (int mi = 0; mi < 4; mi++)
#pragma unroll
        for (int ni = 0; ni < 4; ni++) {
            size_t idx = ((size_t)h*L_ + i0 + ty*4 + mi)*L_ + j0 + tx*4 + ni;
            g_attn[idx] = acc[mi][ni] + g_bh[idx];
        }
}

// ---------------- E: softmax over j + post-softmax additive mask ----------------
__global__ void kE(const float* __restrict__ mask) {
    int b = blockIdx.x;               // b = h*L + i
    int h = b / L_;  (void)h;
    int i = b - (b / L_) * L_;
    float* row = g_attn + (size_t)b * L_;
    int t = threadIdx.x;              // 128 threads
    float v[3];
    float mx = -1e30f;
#pragma unroll
    for (int u = 0; u < 3; u++) { v[u] = row[t + 128*u]; mx = fmaxf(mx, v[u]); }
    __shared__ float sm[4], ssum[4];
#pragma unroll
    for (int o = 16; o; o >>= 1) mx = fmaxf(mx, __shfl_xor_sync(0xffffffffu, mx, o));
    if ((t & 31) == 0) sm[t >> 5] = mx;
    __syncthreads();
    mx = fmaxf(fmaxf(sm[0], sm[1]), fmaxf(sm[2], sm[3]));
    float s = 0.f;
#pragma unroll
    for (int u = 0; u < 3; u++) { v[u] = expf(v[u] - mx); s += v[u]; }
#pragma unroll
    for (int o = 16; o; o >>= 1) s += __shfl_xor_sync(0xffffffffu, s, o);
    if ((t & 31) == 0) ssum[t >> 5] = s;
    __syncthreads();
    s = ssum[0] + ssum[1] + ssum[2] + ssum[3];
    float inv = 1.f / s;
#pragma unroll
    for (int u = 0; u < 3; u++) {
        int j = t + 128*u;
        row[j] = v[u]*inv + INF_ * (mask[(size_t)i*L_ + j] - 1.f);
    }
}

// ---------------- F: out = attn @ v per (n,h), gated ----------------
__global__ void kF() {
    int h = blockIdx.z, n = blockIdx.y, i0 = blockIdx.x * 64;
    const float* A = g_attn + (size_t)h * L_ * L_;              // [i][j]
    const float* V = g_v + ((size_t)n*NH + h) * L_ * DH;        // [j][d]
    __shared__ float As[64][33];
    __shared__ float Vs[32][48];
    int tx = threadIdx.x /*0..11 -> d*/, ty = threadIdx.y /*0..15 -> i*/;
    int tid = ty*12 + tx;
    float acc[4][4] = {};
    for (int jt = 0; jt < 12; jt++) {
        for (int e = tid; e < 2048; e += 192) {
            int ii = e >> 5, jj = e & 31;
            As[ii][jj] = A[(size_t)(i0+ii)*L_ + jt*32 + jj];
        }
        for (int e = tid; e < 1536; e += 192) {
            int jj = e / 48, d = e - jj*48;
            Vs[jj][d] = V[(size_t)(jt*32 + jj)*DH + d];
        }
        __syncthreads();
#pragma unroll
        for (int jj = 0; jj < 32; jj++) {
            float4 v4 = *(const float4*)&Vs[jj][tx*4];
            float a;
            a = As[ty*4+0][jj]; acc[0][0]+=a*v4.x; acc[0][1]+=a*v4.y; acc[0][2]+=a*v4.z; acc[0][3]+=a*v4.w;
            a = As[ty*4+1][jj]; acc[1][0]+=a*v4.x; acc[1][1]+=a*v4.y; acc[1][2]+=a*v4.z; acc[1][3]+=a*v4.w;
            a = As[ty*4+2][jj]; acc[2][0]+=a*v4.x; acc[2][1]+=a*v4.y; acc[2][2]+=a*v4.z; acc[2][3]+=a*v4.w;
            a = As[ty*4+3][jj]; acc[3][0]+=a*v4.x; acc[3][1]+=a*v4.y; acc[3][2]+=a*v4.z; acc[3][3]+=a*v4.w;
        }
        __syncthreads();
    }
#pragma unroll
    for (int mi = 0; mi < 4; mi++) {
        int r = n*L_ + i0 + ty*4 + mi;
#pragma unroll
        for (int ni = 0; ni < 4; ni++) {
            int c = h*DH + tx*4 + ni;
            g_og[(size_t)r*HD + c] = acc[mi][ni] * g_gate[(size_t)r*HD + c];
        }
    }
}

// ---------------- G: final projection [147456,192]@[192,128] + output transpose ----------------
__global__ void kG(const float* __restrict__ Wo, float* __restrict__ out) {
    int r0 = blockIdx.x * 64, c0 = blockIdx.y * 64;
    __shared__ float As[64][65];   // [k][m]
    __shared__ float Bs[64][64];   // [k][n]
    int tx = threadIdx.x, ty = threadIdx.y, tid = ty*16 + tx;
    float acc[4][4] = {};
    for (int kt = 0; kt < 3; kt++) {
        int k0 = kt * 64;
        for (int e = tid; e < 4096; e += 256) {
            int m = e >> 6, kk = e & 63;
            As[kk][m] = g_og[(size_t)(r0+m)*HD + k0 + kk];
        }
        for (int e = tid; e < 4096; e += 256) {
            int kk = e >> 6, cn = e & 63;
            Bs[kk][cn] = Wo[(size_t)(k0+kk)*DE + c0 + cn];
        }
        __syncthreads();
#pragma unroll
        for (int kk = 0; kk < 64; kk++) {
            float4 b4 = *(const float4*)&Bs[kk][tx*4];
            float a;
            a = As[kk][ty*4+0]; acc[0][0]+=a*b4.x; acc[0][1]+=a*b4.y; acc[0][2]+=a*b4.z; acc[0][3]+=a*b4.w;
            a = As[kk][ty*4+1]; acc[1][0]+=a*b4.x; acc[1][1]+=a*b4.y; acc[1][2]+=a*b4.z; acc[1][3]+=a*b4.w;
            a = As[kk][ty*4+2]; acc[2][0]+=a*b4.x; acc[2][1]+=a*b4.y; acc[2][2]+=a*b4.z; acc[2][3]+=a*b4.w;
            a = As[kk][ty*4+3]; acc[3][0]+=a*b4.x; acc[3][1]+=a*b4.y; acc[3][2]+=a*b4.z; acc[3][3]+=a*b4.w;
        }
        __syncthreads();
    }
    int n = r0 / L_;
    int ibase = r0 - n * L_;
#pragma unroll
    for (int mi = 0; mi < 4; mi++) {
        int i = ibase + ty*4 + mi;
#pragma unroll
        for (int ni = 0; ni < 4; ni++) {
            out[((size_t)i*L_ + n)*DE + c0 + tx*4 + ni] = acc[mi][ni];   // undo row permute
        }
    }
}

// ---------------- launch ----------------
extern "C" void kernel_launch(void* const* d_in, const int* in_sizes, int n_in,
                              void* d_out, int out_size) {
    const float* edge  = (const float*)d_in[0];
    const float* bias  = (const float*)d_in[1];
    const int*   epos  = (const int*)  d_in[2];
    const float* emask = (const float*)d_in[3];
    const float* lneg  = (const float*)d_in[4];
    const float* lneb  = (const float*)d_in[5];
    const float* lnbg  = (const float*)d_in[6];
    const float* lnbb  = (const float*)d_in[7];
    const float* Wq    = (const float*)d_in[8];
    const float* Wk    = (const float*)d_in[9];
    const float* Wv    = (const float*)d_in[10];
    const float* Wb    = (const float*)d_in[11];
    const float* Wg    = (const float*)d_in[12];
    const float* bg    = (const float*)d_in[13];
    const float* Wo    = (const float*)d_in[14];
    float* out = (float*)d_out;

    dim3 b32x8(32, 8);
    kA<<<NPAIR/8, b32x8>>>(edge, lneg, lneb);
    kB<<<NPAIR/8, b32x8>>>(bias, lnbg, lnbb, Wb);
    kC<<<dim3(NPAIR/64, 3, 4), dim3(16,16)>>>(Wq, Wk, Wv, Wg, bg);
    kC2<<<(2*NH*L_*24*L_)/256, 256>>>(epos);
    kD<<<dim3(6, 6, NH), dim3(16,16)>>>();
    kE<<<NH*L_, 128>>>(emask);
    kF<<<dim3(6, L_, NH), dim3(12,16)>>>();
    kG<<<dim3(NPAIR/64, 2), dim3(16,16)>>>(Wo, out);
}

// round 6
// speedup vs baseline: 1.9698x; 1.9691x over previous
#include <cuda_runtime.h>
#include <cuda_bf16.h>
#include <stdint.h>
#include <math.h>

#define L_      384
#define DE      128
#define DB      64
#define NH      4
#define DH      48
#define HD      (NH*DH)        // 192
#define NPAIR   (L_*L_)        // 147456
#define NK      (L_*DH)        // 18432
#define EPS_    1e-5f
#define INF_    1000000.0f
#define SCALE_  0.14433756729740643f   // 1/sqrt(48)

// ---------------- scratch ----------------
__device__ float g_eln [(size_t)NPAIR*DE];
__device__ float g_q2  [(size_t)NH*L_*NK];          // [h][i][n*48+d] fp32 pre-RoPE
__device__ float g_k2  [(size_t)NH*L_*NK];
__device__ __nv_bfloat16 g_qb[(size_t)NH*L_*NK];    // post-RoPE * SCALE
__device__ __nv_bfloat16 g_kb[(size_t)NH*L_*NK];    // post-RoPE / L
__device__ float g_v   [(size_t)L_*NH*L_*DH];       // [n][h][j][d]
__device__ __nv_bfloat16 g_vThi[(size_t)NH*NK*L_];  // [h][n*48+d][j]
__device__ __nv_bfloat16 g_vTlo[(size_t)NH*NK*L_];
__device__ float g_gateT[(size_t)HD*NPAIR];         // [h*48+d][n*L+i]
__device__ float g_bh  [NH*L_*L_];                  // [h][i][j]
__device__ float g_attn[NH*L_*L_];
__device__ __nv_bfloat16 g_ahi[NH*L_*L_];
__device__ __nv_bfloat16 g_alo[NH*L_*L_];
__device__ float g_ogT [(size_t)HD*NPAIR];          // [h*48+d][n*L+i]
__device__ float g_tc  [L_*24];
__device__ float g_ts  [L_*24];

// ================= warp-MMA helpers (plain sm_103-safe) =================
__device__ __forceinline__ uint32_t smem_u32(const void* p){
    uint32_t a;
    asm("{ .reg .u64 t; cvta.to.shared.u64 t, %1; cvt.u32.u64 %0, t; }" : "=r"(a) : "l"(p));
    return a;
}
__device__ __forceinline__ void ldsm4(uint32_t* r, uint32_t addr){
    asm volatile("ldmatrix.sync.aligned.m8n8.x4.shared.b16 {%0,%1,%2,%3}, [%4];"
        : "=r"(r[0]),"=r"(r[1]),"=r"(r[2]),"=r"(r[3]) : "r"(addr));
}
__device__ __forceinline__ void ldsm2(uint32_t* r, uint32_t addr){
    asm volatile("ldmatrix.sync.aligned.m8n8.x2.shared.b16 {%0,%1}, [%2];"
        : "=r"(r[0]),"=r"(r[1]) : "r"(addr));
}
__device__ __forceinline__ void mma16816(float* c, const uint32_t* a, const uint32_t* b){
    asm volatile("mma.sync.aligned.m16n8k16.row.col.f32.bf16.bf16.f32 "
        "{%0,%1,%2,%3}, {%4,%5,%6,%7}, {%8,%9}, {%0,%1,%2,%3};"
        : "+f"(c[0]), "+f"(c[1]), "+f"(c[2]), "+f"(c[3])
        : "r"(a[0]), "r"(a[1]), "r"(a[2]), "r"(a[3]), "r"(b[0]), "r"(b[1]));
}
__device__ __forceinline__ void cpa16(uint32_t saddr, const void* g){
    asm volatile("cp.async.cg.shared.global [%0], [%1], 16;" :: "r"(saddr), "l"(g));
}
#define CP_COMMIT() asm volatile("cp.async.commit_group;" ::: "memory")
#define CP_WAIT0()  asm volatile("cp.async.wait_group 0;" ::: "memory")

#define TSTRIDE 40   // bf16 elems per smem tile row (80B): conflict-free ldmatrix
#define TILEB   (128*TSTRIDE*2)  // 10240 bytes per 128x32 bf16 tile

// ---------------- A: layernorm of transposed edge ----------------
__global__ void kA(const float* __restrict__ edge, const float* __restrict__ gg,
                   const float* __restrict__ bb) {
    int row  = blockIdx.x * 8 + threadIdx.y;          // r = n*L + i
    int n    = row / L_;
    int i    = row - n * L_;
    int lane = threadIdx.x;
    const float* x = edge + ((size_t)i * L_ + n) * DE;
    float v[4], s = 0.f, s2 = 0.f;
#pragma unroll
    for (int t = 0; t < 4; t++) {
        float xv = x[lane + 32*t];
        v[t] = xv; s += xv; s2 += xv*xv;
    }
#pragma unroll
    for (int o = 16; o; o >>= 1) {
        s  += __shfl_xor_sync(0xffffffffu, s,  o);
        s2 += __shfl_xor_sync(0xffffffffu, s2, o);
    }
    float mu = s * (1.f/DE);
    float var = s2 * (1.f/DE) - mu*mu;
    float r = rsqrtf(var + EPS_);
    float* y = g_eln + (size_t)row * DE;
#pragma unroll
    for (int t = 0; t < 4; t++) {
        int c = lane + 32*t;
        y[c] = (v[t]-mu)*r*gg[c] + bb[c];
    }
}

// ---------------- B: layernorm of transposed bias + Wb -> b_h[h][i][j] ----------------
__global__ void kB(const float* __restrict__ bias, const float* __restrict__ gg,
                   const float* __restrict__ bb, const float* __restrict__ Wb) {
    int p = blockIdx.x * 8 + threadIdx.y;             // p = i*L + j
    int i = p / L_;
    int j = p - i * L_;
    int lane = threadIdx.x;
    const float* x = bias + ((size_t)j * L_ + i) * DB;
    float x0 = x[lane], x1 = x[lane+32];
    float s = x0 + x1, s2 = x0*x0 + x1*x1;
#pragma unroll
    for (int o = 16; o; o >>= 1) {
        s  += __shfl_xor_sync(0xffffffffu, s,  o);
        s2 += __shfl_xor_sync(0xffffffffu, s2, o);
    }
    float mu = s * (1.f/DB);
    float var = s2 * (1.f/DB) - mu*mu;
    float r = rsqrtf(var + EPS_);
    float y0 = (x0-mu)*r*gg[lane]    + bb[lane];
    float y1 = (x1-mu)*r*gg[lane+32] + bb[lane+32];
    float a[4];
#pragma unroll
    for (int h = 0; h < 4; h++)
        a[h] = y0 * Wb[lane*NH + h] + y1 * Wb[(lane+32)*NH + h];
#pragma unroll
    for (int h = 0; h < 4; h++)
#pragma unroll
        for (int o = 16; o; o >>= 1)
            a[h] += __shfl_xor_sync(0xffffffffu, a[h], o);
    if (lane < 4)
        g_bh[((size_t)lane * L_ + i) * L_ + j] = a[lane];
}

// ---------------- RoPE table ----------------
__global__ void kRope(const int* __restrict__ pos) {
    int t = blockIdx.x * 256 + threadIdx.x;
    if (t >= L_*24) return;
    int i = t / 24, d = t - (t/24)*24;
    float ang = (float)pos[i] * powf(10000.f, -(float)d * (1.f/24.f));
    float sn, cs; sincosf(ang, &sn, &cs);
    g_tc[t] = cs; g_ts[t] = sn;
}

// ---------------- C: QKVG projections (SIMT fp32) ----------------
__global__ void kC(const float* __restrict__ Wq, const float* __restrict__ Wk,
                   const float* __restrict__ Wv, const float* __restrict__ Wg,
                   const float* __restrict__ bg) {
    int mode = blockIdx.z;
    const float* W = (mode == 0) ? Wq : (mode == 1) ? Wk : (mode == 2) ? Wv : Wg;
    int r0 = blockIdx.x * 64, c0 = blockIdx.y * 64;
    __shared__ float As[64][65];   // [k][m]
    __shared__ float Bs[64][64];   // [k][n]
    int tx = threadIdx.x, ty = threadIdx.y, tid = ty*16 + tx;
    float acc[4][4] = {};
    for (int kt = 0; kt < 2; kt++) {
        int k0 = kt * 64;
        for (int e = tid; e < 4096; e += 256) {
            int m = e >> 6, kk = e & 63;
            As[kk][m] = g_eln[(size_t)(r0+m)*DE + k0 + kk];
        }
        for (int e = tid; e < 4096; e += 256) {
            int kk = e >> 6, cn = e & 63;
            Bs[kk][cn] = W[(size_t)(k0+kk)*HD + c0 + cn];
        }
        __syncthreads();
#pragma unroll
        for (int kk = 0; kk < 64; kk++) {
            float4 b4 = *(const float4*)&Bs[kk][tx*4];
            float a;
            a = As[kk][ty*4+0]; acc[0][0]+=a*b4.x; acc[0][1]+=a*b4.y; acc[0][2]+=a*b4.z; acc[0][3]+=a*b4.w;
            a = As[kk][ty*4+1]; acc[1][0]+=a*b4.x; acc[1][1]+=a*b4.y; acc[1][2]+=a*b4.z; acc[1][3]+=a*b4.w;
            a = As[kk][ty*4+2]; acc[2][0]+=a*b4.x; acc[2][1]+=a*b4.y; acc[2][2]+=a*b4.z; acc[2][3]+=a*b4.w;
            a = As[kk][ty*4+3]; acc[3][0]+=a*b4.x; acc[3][1]+=a*b4.y; acc[3][2]+=a*b4.z; acc[3][3]+=a*b4.w;
        }
        __syncthreads();
    }
    int n = r0 / L_;               // 64 | 384 -> tile shares n
    int ibase = r0 - n * L_;
    if (mode == 3) {
        __syncthreads();
#pragma unroll
        for (int mi = 0; mi < 4; mi++)
#pragma unroll
            for (int ni = 0; ni < 4; ni++) {
                int c = c0 + tx*4 + ni;
                Bs[tx*4+ni][ty*4+mi] = 1.f / (1.f + expf(-(acc[mi][ni] + bg[c])));
            }
        __syncthreads();
        for (int e = tid; e < 4096; e += 256) {
            int cl = e >> 6, rl = e & 63;
            g_gateT[(size_t)(c0+cl)*NPAIR + r0 + rl] = Bs[cl][rl];
        }
        return;
    }
#pragma unroll
    for (int mi = 0; mi < 4; mi++) {
        int i = ibase + ty*4 + mi;
#pragma unroll
        for (int ni = 0; ni < 4; ni++) {
            int c = c0 + tx*4 + ni;
            float val = acc[mi][ni];
            int h = c / DH, d = c - h*DH;
            if (mode == 0)      g_q2[((size_t)h*L_ + i)*NK + (size_t)n*DH + d] = val;
            else if (mode == 1) g_k2[((size_t)h*L_ + i)*NK + (size_t)n*DH + d] = val;
            else                g_v[(((size_t)n*NH + h)*L_ + i)*DH + d] = val;  // i==j here
        }
    }
}

// ---------------- C2: RoPE via table + scale -> bf16 ----------------
__global__ void kC2() {
    int t = blockIdx.x * 256 + threadIdx.x;
    int d = t % 24; int rest = t / 24;
    int n = rest % L_; rest /= L_;
    int i = rest % L_; rest /= L_;
    int h = rest % NH;
    int side = rest / NH;
    const float* P = side ? g_k2 : g_q2;
    __nv_bfloat16* O = side ? g_kb : g_qb;
    size_t base = ((size_t)h*L_ + i)*NK + (size_t)n*DH + d;
    float x1 = P[base], x2 = P[base + 24];
    float cs = g_tc[i*24 + d], sn = g_ts[i*24 + d];
    float sc = side ? (1.f/(float)L_) : SCALE_;
    O[base]      = __float2bfloat16((x1*cs - x2*sn) * sc);
    O[base + 24] = __float2bfloat16((x1*sn + x2*cs) * sc);
}

// ---------------- Tv: v [n][h][j][d] -> vT hi/lo [h][n*48+d][j] ----------------
__global__ void kTv() {
    int jc = blockIdx.x * 128;
    int nh = blockIdx.y;
    int n = nh / NH, h = nh - n*NH;
    __shared__ float s[48][129];
    int tid = threadIdx.x;
    const float* src = g_v + ((size_t)nh * L_ + jc) * DH;
    for (int e = tid; e < 128*48; e += 256) {
        int jj = e / 48, d = e - jj*48;
        s[d][jj] = src[e];
    }
    __syncthreads();
    for (int e = tid; e < 48*128; e += 256) {
        int d = e >> 7, jj = e & 127;
        float x = s[d][jj];
        __nv_bfloat16 hi = __float2bfloat16(x);
        float lo = x - __bfloat162float(hi);
        size_t o = ((size_t)h*NK + (size_t)n*DH + d) * L_ + jc + jj;
        g_vThi[o] = hi;
        g_vTlo[o] = __float2bfloat16(lo);
    }
}

// ---------------- Dm: logits GEMM per head via mma.sync bf16, + bias ----------------
__global__ void __launch_bounds__(256) kDm() {
    __shared__ __align__(16) __nv_bfloat16 sA[2][128*TSTRIDE];
    __shared__ __align__(16) __nv_bfloat16 sB[2][128*TSTRIDE];
    int h = blockIdx.z, i0 = blockIdx.y*128, j0 = blockIdx.x*128;
    int tid = threadIdx.x, w = tid >> 5, lane = tid & 31;
    int wy = w >> 2, wx = w & 3;           // warp tile: rows wy*64..+63, cols wx*32..+31
    uint32_t sbA = smem_u32(sA), sbB = smem_u32(sB);
    const __nv_bfloat16* Ag = g_qb + (size_t)(h*L_ + i0)*NK;
    const __nv_bfloat16* Bg = g_kb + (size_t)(h*L_ + j0)*NK;
    // per-thread cp.async assignment: 2 quads A + 2 quads B per chunk
    int rowA[2], segA[2];
#pragma unroll
    for (int u = 0; u < 2; u++) { int e = tid + 256*u; rowA[u] = e >> 2; segA[u] = e & 3; }
    float acc[4][4][4] = {};
    // preload chunk 0
#pragma unroll
    for (int u = 0; u < 2; u++) {
        cpa16(sbA + (rowA[u]*TSTRIDE + segA[u]*8)*2, Ag + (size_t)rowA[u]*NK + segA[u]*8);
        cpa16(sbB + (rowA[u]*TSTRIDE + segA[u]*8)*2, Bg + (size_t)rowA[u]*NK + segA[u]*8);
    }
    CP_COMMIT();
    CP_WAIT0();
    __syncthreads();
    for (int kt = 0; kt < 576; kt++) {
        int cur = kt & 1;
        if (kt + 1 < 576) {
            int nb = cur ^ 1;
            int kofs = (kt+1)*32;
#pragma unroll
            for (int u = 0; u < 2; u++) {
                cpa16(sbA + nb*TILEB + (rowA[u]*TSTRIDE + segA[u]*8)*2, Ag + (size_t)rowA[u]*NK + kofs + segA[u]*8);
                cpa16(sbB + nb*TILEB + (rowA[u]*TSTRIDE + segA[u]*8)*2, Bg + (size_t)rowA[u]*NK + kofs + segA[u]*8);
            }
            CP_COMMIT();
        }
#pragma unroll
        for (int ks = 0; ks < 2; ks++) {
            uint32_t bfr[4][2];
#pragma unroll
            for (int nt = 0; nt < 4; nt++)
                ldsm2(bfr[nt], sbB + cur*TILEB + ((wx*32 + nt*8 + (lane&7))*TSTRIDE + ks*16 + (lane&8))*2);
#pragma unroll
            for (int mt = 0; mt < 4; mt++) {
                uint32_t af[4];
                ldsm4(af, sbA + cur*TILEB + ((wy*64 + mt*16 + (lane&15))*TSTRIDE + ks*16 + ((lane>>4)<<3))*2);
#pragma unroll
                for (int nt = 0; nt < 4; nt++)
                    mma16816(acc[mt][nt], af, bfr[nt]);
            }
        }
        if (kt + 1 < 576) CP_WAIT0();
        __syncthreads();
    }
    // epilogue: + bias, direct store
#pragma unroll
    for (int mt = 0; mt < 4; mt++) {
        int r = i0 + wy*64 + mt*16 + (lane>>2);
#pragma unroll
        for (int nt = 0; nt < 4; nt++) {
            int c = j0 + wx*32 + nt*8 + (lane&3)*2;
            size_t base = ((size_t)(h*L_ + r))*L_ + c;
            g_attn[base]   = acc[mt][nt][0] + g_bh[base];
            g_attn[base+1] = acc[mt][nt][1] + g_bh[base+1];
            size_t b8 = base + (size_t)8*L_;
            g_attn[b8]   = acc[mt][nt][2] + g_bh[b8];
            g_attn[b8+1] = acc[mt][nt][3] + g_bh[b8+1];
        }
    }
}

// ---------------- E: softmax over j + post-softmax mask -> hi/lo bf16 ----------------
__global__ void kE(const float* __restrict__ mask) {
    int b = blockIdx.x;               // b = h*L + i
    int i = b - (b / L_) * L_;
    float* row = g_attn + (size_t)b * L_;
    int t = threadIdx.x;              // 128 threads
    float v[3];
    float mx = -1e30f;
#pragma unroll
    for (int u = 0; u < 3; u++) { v[u] = row[t + 128*u]; mx = fmaxf(mx, v[u]); }
    __shared__ float smx[4], ssum[4];
#pragma unroll
    for (int o = 16; o; o >>= 1) mx = fmaxf(mx, __shfl_xor_sync(0xffffffffu, mx, o));
    if ((t & 31) == 0) smx[t >> 5] = mx;
    __syncthreads();
    mx = fmaxf(fmaxf(smx[0], smx[1]), fmaxf(smx[2], smx[3]));
    float s = 0.f;
#pragma unroll
    for (int u = 0; u < 3; u++) { v[u] = expf(v[u] - mx); s += v[u]; }
#pragma unroll
    for (int o = 16; o; o >>= 1) s += __shfl_xor_sync(0xffffffffu, s, o);
    if ((t & 31) == 0) ssum[t >> 5] = s;
    __syncthreads();
    s = ssum[0] + ssum[1] + ssum[2] + ssum[3];
    float inv = 1.f / s;
#pragma unroll
    for (int u = 0; u < 3; u++) {
        int j = t + 128*u;
        float p = v[u]*inv + INF_ * (mask[(size_t)i*L_ + j] - 1.f);
        __nv_bfloat16 hi = __float2bfloat16(p);
        g_ahi[(size_t)b*L_ + j] = hi;
        g_alo[(size_t)b*L_ + j] = __float2bfloat16(p - __bfloat162float(hi));
    }
}

// ---------------- Fm: AV via mma.sync split-bf16, gated, writes ogT ----------------
__global__ void __launch_bounds__(256) kFm() {
    extern __shared__ __align__(16) char dyn[];
    // layout: buf b (0/1): mats Ah,Al,Bh,Bl at b*4*TILEB + mat*TILEB
    int h = blockIdx.z, i0 = blockIdx.y*128, C0 = blockIdx.x*128;
    int tid = threadIdx.x, w = tid >> 5, lane = tid & 31;
    int wy = w >> 2, wx = w & 3;
    uint32_t sb = smem_u32(dyn);
    const __nv_bfloat16* M0 = g_ahi  + (size_t)(h*L_ + i0)*L_;
    const __nv_bfloat16* M1 = g_alo  + (size_t)(h*L_ + i0)*L_;
    const __nv_bfloat16* M2 = g_vThi + ((size_t)h*NK + C0)*L_;
    const __nv_bfloat16* M3 = g_vTlo + ((size_t)h*NK + C0)*L_;
    const __nv_bfloat16* Ms[4] = {M0, M1, M2, M3};
    float acc[4][4][4] = {};
    // per-thread cp.async: 8 quads (4 mats x 512 quads / 256 threads)
    auto issue = [&](int buf, int kofs) {
#pragma unroll
        for (int u = 0; u < 8; u++) {
            int e = tid + 256*u;
            int mat = e >> 9, rem = e & 511;
            int row = rem >> 2, seg = rem & 3;
            cpa16(sb + buf*(4*TILEB) + mat*TILEB + (row*TSTRIDE + seg*8)*2,
                  Ms[mat] + (size_t)row*L_ + kofs + seg*8);
        }
        CP_COMMIT();
    };
    issue(0, 0);
    CP_WAIT0();
    __syncthreads();
    for (int kt = 0; kt < 12; kt++) {
        int cur = kt & 1;
        if (kt + 1 < 12) issue(cur ^ 1, (kt+1)*32);
        uint32_t base = sb + cur*(4*TILEB);
#pragma unroll
        for (int ks = 0; ks < 2; ks++) {
            uint32_t bh[4][2], bl[4][2];
#pragma unroll
            for (int nt = 0; nt < 4; nt++) {
                uint32_t ro = ((wx*32 + nt*8 + (lane&7))*TSTRIDE + ks*16 + (lane&8))*2;
                ldsm2(bh[nt], base + 2*TILEB + ro);
                ldsm2(bl[nt], base + 3*TILEB + ro);
            }
#pragma unroll
            for (int mt = 0; mt < 4; mt++) {
                uint32_t ah[4], al[4];
                uint32_t ro = ((wy*64 + mt*16 + (lane&15))*TSTRIDE + ks*16 + ((lane>>4)<<3))*2;
                ldsm4(ah, base + 0*TILEB + ro);
                ldsm4(al, base + 1*TILEB + ro);
#pragma unroll
                for (int nt = 0; nt < 4; nt++) {
                    mma16816(acc[mt][nt], ah, bh[nt]);
                    mma16816(acc[mt][nt], ah, bl[nt]);
                    mma16816(acc[mt][nt], al, bh[nt]);
                }
            }
        }
        if (kt + 1 < 12) CP_WAIT0();
        __syncthreads();
    }
    // epilogue: stage [c][i] through smem in two 64-col halves, gated coalesced writes
    float* ss = (float*)dyn;            // 64 x 130 floats = 33280B (fits in 80KB)
#pragma unroll
    for (int half = 0; half < 2; half++) {
        __syncthreads();
        if ((wx >> 1) == half) {
            int cl0 = (wx & 1)*32;
#pragma unroll
            for (int mt = 0; mt < 4; mt++) {
                int il = wy*64 + mt*16 + (lane>>2);
#pragma unroll
                for (int nt = 0; nt < 4; nt++) {
                    int cl = cl0 + nt*8 + (lane&3)*2;
                    ss[cl*130 + il]       = acc[mt][nt][0];
                    ss[(cl+1)*130 + il]   = acc[mt][nt][1];
                    ss[cl*130 + il+8]     = acc[mt][nt][2];
                    ss[(cl+1)*130 + il+8] = acc[mt][nt][3];
                }
            }
        }
        __syncthreads();
        {
            int cl = tid >> 2, seg = tid & 3;
            int C = C0 + half*64 + cl;
            int n = C / DH, d = C - n*DH;
            size_t gbase = ((size_t)(h*DH + d))*NPAIR + (size_t)n*L_ + i0 + seg*32;
            const float* srow = ss + cl*130 + seg*32;
#pragma unroll
            for (int u = 0; u < 8; u++) {
                float4 o;
                o.x = srow[u*4+0] * g_gateT[gbase + u*4+0];
                o.y = srow[u*4+1] * g_gateT[gbase + u*4+1];
                o.z = srow[u*4+2] * g_gateT[gbase + u*4+2];
                o.w = srow[u*4+3] * g_gateT[gbase + u*4+3];
                *(float4*)(g_ogT + gbase + u*4) = o;
            }
        }
    }
}

// ---------------- G: final projection (reads ogT) + output transpose ----------------
__global__ void kG(const float* __restrict__ Wo, float* __restrict__ out) {
    int r0 = blockIdx.x * 64, c0 = blockIdx.y * 64;
    __shared__ float As[64][65];   // [k][m]
    __shared__ float Bs[64][64];   // [k][n]
    int tx = threadIdx.x, ty = threadIdx.y, tid = ty*16 + tx;
    float acc[4][4] = {};
    for (int kt = 0; kt < 3; kt++) {
        int k0 = kt * 64;
        for (int e = tid; e < 4096; e += 256) {
            int kk = e >> 6, m = e & 63;
            As[kk][m] = g_ogT[(size_t)(k0+kk)*NPAIR + r0 + m];
        }
        for (int e = tid; e < 4096; e += 256) {
            int kk = e >> 6, cn = e & 63;
            Bs[kk][cn] = Wo[(size_t)(k0+kk)*DE + c0 + cn];
        }
        __syncthreads();
#pragma unroll
        for (int kk = 0; kk < 64; kk++) {
            float4 b4 = *(const float4*)&Bs[kk][tx*4];
            float a;
            a = As[kk][ty*4+0]; acc[0][0]+=a*b4.x; acc[0][1]+=a*b4.y; acc[0][2]+=a*b4.z; acc[0][3]+=a*b4.w;
            a = As[kk][ty*4+1]; acc[1][0]+=a*b4.x; acc[1][1]+=a*b4.y; acc[1][2]+=a*b4.z; acc[1][3]+=a*b4.w;
            a = As[kk][ty*4+2]; acc[2][0]+=a*b4.x; acc[2][1]+=a*b4.y; acc[2][2]+=a*b4.z; acc[2][3]+=a*b4.w;
            a = As[kk][ty*4+3]; acc[3][0]+=a*b4.x; acc[3][1]+=a*b4.y; acc[3][2]+=a*b4.z; acc[3][3]+=a*b4.w;
        }
        __syncthreads();
    }
    int n = r0 / L_;
    int ibase = r0 - n * L_;
#pragma unroll
    for (int mi = 0; mi < 4; mi++) {
        int i = ibase + ty*4 + mi;
#pragma unroll
        for (int ni = 0; ni < 4; ni++) {
            out[((size_t)i*L_ + n)*DE + c0 + tx*4 + ni] = acc[mi][ni];
        }
    }
}

// ---------------- launch ----------------
extern "C" void kernel_launch(void* const* d_in, const int* in_sizes, int n_in,
                              void* d_out, int out_size) {
    const float* edge  = (const float*)d_in[0];
    const float* bias  = (const float*)d_in[1];
    const int*   epos  = (const int*)  d_in[2];
    const float* emask = (const float*)d_in[3];
    const float* lneg  = (const float*)d_in[4];
    const float* lneb  = (const float*)d_in[5];
    const float* lnbg  = (const float*)d_in[6];
    const float* lnbb  = (const float*)d_in[7];
    const float* Wq    = (const float*)d_in[8];
    const float* Wk    = (const float*)d_in[9];
    const float* Wv    = (const float*)d_in[10];
    const float* Wb    = (const float*)d_in[11];
    const float* Wg    = (const float*)d_in[12];
    const float* bg    = (const float*)d_in[13];
    const float* Wo    = (const float*)d_in[14];
    float* out = (float*)d_out;

    cudaFuncSetAttribute(kFm, cudaFuncAttributeMaxDynamicSharedMemorySize, 8*TILEB);

    dim3 b32x8(32, 8);
    kA<<<NPAIR/8, b32x8>>>(edge, lneg, lneb);
    kB<<<NPAIR/8, b32x8>>>(bias, lnbg, lnbb, Wb);
    kRope<<<36, 256>>>(epos);
    kC<<<dim3(NPAIR/64, 3, 4), dim3(16,16)>>>(Wq, Wk, Wv, Wg, bg);
    kC2<<<(2*NH*L_*L_*24)/256, 256>>>();
    kTv<<<dim3(3, L_*NH), 256>>>();
    kDm<<<dim3(3, 3, NH), 256>>>();
    kE<<<NH*L_, 128>>>(emask);
    kFm<<<dim3(NK/128, 3, NH), 256, 8*TILEB>>>();
    kG<<<dim3(NPAIR/64, 2), dim3(16,16)>>>(Wo, out);
}

// round 7
// speedup vs baseline: 3.0653x; 1.5561x over previous
#include <cuda_runtime.h>
#include <cuda_bf16.h>
#include <stdint.h>
#include <math.h>

#define L_      384
#define DE      128
#define DB      64
#define NH      4
#define DH      48
#define HD      (NH*DH)        // 192
#define NPAIR   (L_*L_)        // 147456
#define NK      (L_*DH)        // 18432
#define EPS_    1e-5f
#define INF_    1000000.0f
#define SCALE_  0.14433756729740643f   // 1/sqrt(48)

// ---------------- scratch ----------------
__device__ __nv_bfloat16 g_ehi[(size_t)NPAIR*DE];   // LN(edge^T) split
__device__ __nv_bfloat16 g_elo[(size_t)NPAIR*DE];
__device__ __nv_bfloat16 g_wthi[4*HD*DE];           // W^T [mode][n][k] split
__device__ __nv_bfloat16 g_wtlo[4*HD*DE];
__device__ __nv_bfloat16 g_qb[(size_t)NH*L_*NK];    // [h][i][n*48+d] post-RoPE * SCALE
__device__ __nv_bfloat16 g_kb[(size_t)NH*L_*NK];    // post-RoPE / L
__device__ float g_v   [(size_t)L_*NH*L_*DH];       // [n][h][j][d]
__device__ __nv_bfloat16 g_vThi[(size_t)NH*NK*L_];  // [h][n*48+d][j]
__device__ __nv_bfloat16 g_vTlo[(size_t)NH*NK*L_];
__device__ float g_gateT[(size_t)HD*NPAIR];         // [h*48+d][n*L+i]
__device__ float g_bh  [NH*L_*L_];                  // [h][i][j]
__device__ float g_attn[NH*L_*L_];
__device__ __nv_bfloat16 g_ahi[NH*L_*L_];
__device__ __nv_bfloat16 g_alo[NH*L_*L_];
__device__ float g_ogT [(size_t)HD*NPAIR];          // [h*48+d][n*L+i]
__device__ float g_tc  [L_*24];
__device__ float g_ts  [L_*24];

// ================= warp-MMA helpers =================
__device__ __forceinline__ uint32_t smem_u32(const void* p){
    uint32_t a;
    asm("{ .reg .u64 t; cvta.to.shared.u64 t, %1; cvt.u32.u64 %0, t; }" : "=r"(a) : "l"(p));
    return a;
}
__device__ __forceinline__ void ldsm4(uint32_t* r, uint32_t addr){
    asm volatile("ldmatrix.sync.aligned.m8n8.x4.shared.b16 {%0,%1,%2,%3}, [%4];"
        : "=r"(r[0]),"=r"(r[1]),"=r"(r[2]),"=r"(r[3]) : "r"(addr));
}
__device__ __forceinline__ void ldsm2(uint32_t* r, uint32_t addr){
    asm volatile("ldmatrix.sync.aligned.m8n8.x2.shared.b16 {%0,%1}, [%2];"
        : "=r"(r[0]),"=r"(r[1]) : "r"(addr));
}
__device__ __forceinline__ void mma16816(float* c, const uint32_t* a, const uint32_t* b){
    asm volatile("mma.sync.aligned.m16n8k16.row.col.f32.bf16.bf16.f32 "
        "{%0,%1,%2,%3}, {%4,%5,%6,%7}, {%8,%9}, {%0,%1,%2,%3};"
        : "+f"(c[0]), "+f"(c[1]), "+f"(c[2]), "+f"(c[3])
        : "r"(a[0]), "r"(a[1]), "r"(a[2]), "r"(a[3]), "r"(b[0]), "r"(b[1]));
}
__device__ __forceinline__ void cpa16(uint32_t saddr, const void* g){
    asm volatile("cp.async.cg.shared.global [%0], [%1], 16;" :: "r"(saddr), "l"(g));
}
#define CP_COMMIT() asm volatile("cp.async.commit_group;" ::: "memory")
#define CP_WAIT0()  asm volatile("cp.async.wait_group 0;" ::: "memory")
__device__ __forceinline__ float sigm(float x){ return 1.f/(1.f+expf(-x)); }

#define TSTRIDE 40               // kFm smem row stride (bf16 elems)
#define TILEB   (128*TSTRIDE*2)
#define TS2     136              // kCm row stride (K=128 + pad)
#define DSTRIDE 72               // kDm row stride (K=64 + pad)

// ---------------- A: layernorm of transposed edge -> hi/lo bf16 ----------------
__global__ void kA(const float* __restrict__ edge, const float* __restrict__ gg,
                   const float* __restrict__ bb) {
    int row  = blockIdx.x * 8 + threadIdx.y;          // r = n*L + i
    int n    = row / L_;
    int i    = row - n * L_;
    int lane = threadIdx.x;
    const float* x = edge + ((size_t)i * L_ + n) * DE;
    float v[4], s = 0.f, s2 = 0.f;
#pragma unroll
    for (int t = 0; t < 4; t++) {
        float xv = x[lane + 32*t];
        v[t] = xv; s += xv; s2 += xv*xv;
    }
#pragma unroll
    for (int o = 16; o; o >>= 1) {
        s  += __shfl_xor_sync(0xffffffffu, s,  o);
        s2 += __shfl_xor_sync(0xffffffffu, s2, o);
    }
    float mu = s * (1.f/DE);
    float var = s2 * (1.f/DE) - mu*mu;
    float r = rsqrtf(var + EPS_);
#pragma unroll
    for (int t = 0; t < 4; t++) {
        int c = lane + 32*t;
        float yv = (v[t]-mu)*r*gg[c] + bb[c];
        __nv_bfloat16 hi = __float2bfloat16(yv);
        g_ehi[(size_t)row*DE + c] = hi;
        g_elo[(size_t)row*DE + c] = __float2bfloat16(yv - __bfloat162float(hi));
    }
}

// ---------------- B: layernorm of transposed bias + Wb -> b_h[h][i][j] ----------------
__global__ void kB(const float* __restrict__ bias, const float* __restrict__ gg,
                   const float* __restrict__ bb, const float* __restrict__ Wb) {
    int p = blockIdx.x * 8 + threadIdx.y;             // p = i*L + j
    int i = p / L_;
    int j = p - i * L_;
    int lane = threadIdx.x;
    const float* x = bias + ((size_t)j * L_ + i) * DB;
    float x0 = x[lane], x1 = x[lane+32];
    float s = x0 + x1, s2 = x0*x0 + x1*x1;
#pragma unroll
    for (int o = 16; o; o >>= 1) {
        s  += __shfl_xor_sync(0xffffffffu, s,  o);
        s2 += __shfl_xor_sync(0xffffffffu, s2, o);
    }
    float mu = s * (1.f/DB);
    float var = s2 * (1.f/DB) - mu*mu;
    float r = rsqrtf(var + EPS_);
    float y0 = (x0-mu)*r*gg[lane]    + bb[lane];
    float y1 = (x1-mu)*r*gg[lane+32] + bb[lane+32];
    float a[4];
#pragma unroll
    for (int h = 0; h < 4; h++)
        a[h] = y0 * Wb[lane*NH + h] + y1 * Wb[(lane+32)*NH + h];
#pragma unroll
    for (int h = 0; h < 4; h++)
#pragma unroll
        for (int o = 16; o; o >>= 1)
            a[h] += __shfl_xor_sync(0xffffffffu, a[h], o);
    if (lane < 4)
        g_bh[((size_t)lane * L_ + i) * L_ + j] = a[lane];
}

// ---------------- RoPE table ----------------
__global__ void kRope(const int* __restrict__ pos) {
    int t = blockIdx.x * 256 + threadIdx.x;
    if (t >= L_*24) return;
    int i = t / 24, d = t - (t/24)*24;
    float ang = (float)pos[i] * powf(10000.f, -(float)d * (1.f/24.f));
    float sn, cs; sincosf(ang, &sn, &cs);
    g_tc[t] = cs; g_ts[t] = sn;
}

// ---------------- W: transpose+split weights -> [mode][n][k] ----------------
__global__ void kW(const float* __restrict__ Wq, const float* __restrict__ Wk,
                   const float* __restrict__ Wv, const float* __restrict__ Wg) {
    int mode = blockIdx.y, nn = blockIdx.x, k = threadIdx.x;   // 128 threads
    const float* W = (mode == 0) ? Wq : (mode == 1) ? Wk : (mode == 2) ? Wv : Wg;
    float x = W[(size_t)k*HD + nn];
    __nv_bfloat16 hi = __float2bfloat16(x);
    size_t o = ((size_t)mode*HD + nn)*DE + k;
    g_wthi[o] = hi;
    g_wtlo[o] = __float2bfloat16(x - __bfloat162float(hi));
}

// ---------------- Cm: QKVG projections via mma.sync split-bf16, RoPE fused ----------------
__global__ void __launch_bounds__(256) kCm(const float* __restrict__ bg) {
    extern __shared__ __align__(16) char dyn[];
    __nv_bfloat16* sAh = (__nv_bfloat16*)dyn;
    __nv_bfloat16* sAl = sAh + 128*TS2;
    __nv_bfloat16* sBh = sAl + 128*TS2;
    __nv_bfloat16* sBl = sBh + 192*TS2;
    int r0 = blockIdx.x * 128;
    int tid = threadIdx.x, w = tid >> 5, lane = tid & 31;
    int wy = w >> 2, wx = w & 3;     // 2x4 warps; warp tile 64M x 48N; wx == head
    uint32_t aAh = smem_u32(sAh), aAl = smem_u32(sAl);
    uint32_t aBh = smem_u32(sBh), aBl = smem_u32(sBl);
    int n = r0 / L_;
    int ibase = r0 - n * L_;
    // load A (stays all kernel) + B mode 0
#pragma unroll
    for (int u = 0; u < 8; u++) {
        int e = tid + 256*u; int row = e >> 4, seg = e & 15;
        cpa16(aAh + (row*TS2 + seg*8)*2, g_ehi + (size_t)(r0+row)*DE + seg*8);
        cpa16(aAl + (row*TS2 + seg*8)*2, g_elo + (size_t)(r0+row)*DE + seg*8);
    }
#pragma unroll
    for (int u = 0; u < 12; u++) {
        int e = tid + 256*u; int row = e >> 4, seg = e & 15;
        cpa16(aBh + (row*TS2 + seg*8)*2, g_wthi + (size_t)row*DE + seg*8);
        cpa16(aBl + (row*TS2 + seg*8)*2, g_wtlo + (size_t)row*DE + seg*8);
    }
    CP_COMMIT(); CP_WAIT0(); __syncthreads();

    for (int mode = 0; mode < 4; mode++) {
        float acc[4][6][4];
#pragma unroll
        for (int a1 = 0; a1 < 4; a1++)
#pragma unroll
            for (int a2 = 0; a2 < 6; a2++)
#pragma unroll
                for (int a3 = 0; a3 < 4; a3++) acc[a1][a2][a3] = 0.f;
#pragma unroll
        for (int ks = 0; ks < 8; ks++) {
            uint32_t bh[6][2], bl[6][2];
#pragma unroll
            for (int nt = 0; nt < 6; nt++) {
                uint32_t ro = ((wx*48 + nt*8 + (lane&7))*TS2 + ks*16 + (lane&8))*2;
                ldsm2(bh[nt], aBh + ro);
                ldsm2(bl[nt], aBl + ro);
            }
#pragma unroll
            for (int mt = 0; mt < 4; mt++) {
                uint32_t ah[4], al[4];
                uint32_t ro = ((wy*64 + mt*16 + (lane&15))*TS2 + ks*16 + ((lane>>4)<<3))*2;
                ldsm4(ah, aAh + ro);
                ldsm4(al, aAl + ro);
#pragma unroll
                for (int nt = 0; nt < 6; nt++) {
                    mma16816(acc[mt][nt], ah, bh[nt]);
                    mma16816(acc[mt][nt], ah, bl[nt]);
                    mma16816(acc[mt][nt], al, bh[nt]);
                }
            }
        }
        __syncthreads();
        if (mode < 3) {   // prefetch next mode's B (overlaps epilogue)
#pragma unroll
            for (int u = 0; u < 12; u++) {
                int e = tid + 256*u; int row = e >> 4, seg = e & 15;
                cpa16(aBh + (row*TS2 + seg*8)*2, g_wthi + (size_t)((mode+1)*HD + row)*DE + seg*8);
                cpa16(aBl + (row*TS2 + seg*8)*2, g_wtlo + (size_t)((mode+1)*HD + row)*DE + seg*8);
            }
            CP_COMMIT();
        }
        // ---- epilogues ----
        if (mode <= 1) {               // q/k: in-register RoPE + scale -> bf16
            float sc = (mode == 0) ? SCALE_ : (1.f/(float)L_);
            __nv_bfloat16* O = (mode == 0) ? g_qb : g_kb;
#pragma unroll
            for (int mt = 0; mt < 4; mt++) {
                int il0 = wy*64 + mt*16 + (lane>>2);
#pragma unroll
                for (int hf = 0; hf < 2; hf++) {
                    int i = ibase + il0 + hf*8;
                    size_t base = ((size_t)(wx*L_ + i))*NK + (size_t)n*DH;
#pragma unroll
                    for (int nt = 0; nt < 3; nt++) {
                        int d0 = nt*8 + (lane&3)*2;
                        float x1a = acc[mt][nt  ][hf*2+0], x1b = acc[mt][nt  ][hf*2+1];
                        float x2a = acc[mt][nt+3][hf*2+0], x2b = acc[mt][nt+3][hf*2+1];
                        float c0 = g_tc[i*24+d0],   s0 = g_ts[i*24+d0];
                        float c1 = g_tc[i*24+d0+1], s1 = g_ts[i*24+d0+1];
                        __nv_bfloat162 o1, o2;
                        o1.x = __float2bfloat16((x1a*c0 - x2a*s0)*sc);
                        o1.y = __float2bfloat16((x1b*c1 - x2b*s1)*sc);
                        o2.x = __float2bfloat16((x1a*s0 + x2a*c0)*sc);
                        o2.y = __float2bfloat16((x1b*s1 + x2b*c1)*sc);
                        *(__nv_bfloat162*)(O + base + d0)      = o1;
                        *(__nv_bfloat162*)(O + base + d0 + 24) = o2;
                    }
                }
            }
        } else if (mode == 2) {        // v: fp32 [n][h][j][d]
#pragma unroll
            for (int mt = 0; mt < 4; mt++) {
                int il0 = wy*64 + mt*16 + (lane>>2);
#pragma unroll
                for (int hf = 0; hf < 2; hf++) {
                    int j = ibase + il0 + hf*8;
                    size_t base = (((size_t)n*NH + wx)*L_ + j)*DH;
#pragma unroll
                    for (int nt = 0; nt < 6; nt++) {
                        int d0 = nt*8 + (lane&3)*2;
                        float2 o; o.x = acc[mt][nt][hf*2+0]; o.y = acc[mt][nt][hf*2+1];
                        *(float2*)(g_v + base + d0) = o;
                    }
                }
            }
        } else {                       // gate: sigmoid, stage -> transposed coalesced
            float* ss = (float*)dyn;   // [192][132]
#pragma unroll
            for (int mt = 0; mt < 4; mt++) {
                int il = wy*64 + mt*16 + (lane>>2);
#pragma unroll
                for (int nt = 0; nt < 6; nt++) {
                    int c = wx*48 + nt*8 + (lane&3)*2;
                    float b0 = bg[c], b1 = bg[c+1];
                    ss[(c  )*132 + il    ] = sigm(acc[mt][nt][0] + b0);
                    ss[(c+1)*132 + il    ] = sigm(acc[mt][nt][1] + b1);
                    ss[(c  )*132 + il + 8] = sigm(acc[mt][nt][2] + b0);
                    ss[(c+1)*132 + il + 8] = sigm(acc[mt][nt][3] + b1);
                }
            }
            __syncthreads();
            for (int e = tid; e < 768; e += 256) {
                int cl = e >> 2, seg = e & 3;
                const float* sr = ss + cl*132 + seg*32;
                size_t gb = (size_t)cl*NPAIR + r0 + seg*32;
#pragma unroll
                for (int u = 0; u < 8; u++)
                    *(float4*)(g_gateT + gb + u*4) = *(const float4*)(sr + u*4);
            }
        }
        if (mode < 3) { CP_WAIT0(); __syncthreads(); }
    }
}

// ---------------- Tv: v [n][h][j][d] -> vT hi/lo [h][n*48+d][j] ----------------
__global__ void kTv() {
    int jc = blockIdx.x * 128;
    int nh = blockIdx.y;
    int n = nh / NH, h = nh - n*NH;
    __shared__ float s[48][129];
    int tid = threadIdx.x;
    const float* src = g_v + ((size_t)nh * L_ + jc) * DH;
    for (int e = tid; e < 128*48; e += 256) {
        int jj = e / 48, d = e - jj*48;
        s[d][jj] = src[e];
    }
    __syncthreads();
    for (int e = tid; e < 48*128; e += 256) {
        int d = e >> 7, jj = e & 127;
        float x = s[d][jj];
        __nv_bfloat16 hi = __float2bfloat16(x);
        float lo = x - __bfloat162float(hi);
        size_t o = ((size_t)h*NK + (size_t)n*DH + d) * L_ + jc + jj;
        g_vThi[o] = hi;
        g_vTlo[o] = __float2bfloat16(lo);
    }
}

// ---------------- Dm: logits GEMM 64x64 tiles via mma.sync, + bias ----------------
__global__ void __launch_bounds__(128) kDm() {
    __shared__ __align__(16) __nv_bfloat16 sA[2][64*DSTRIDE];
    __shared__ __align__(16) __nv_bfloat16 sB[2][64*DSTRIDE];
    int h = blockIdx.z, i0 = blockIdx.y*64, j0 = blockIdx.x*64;
    int tid = threadIdx.x, w = tid >> 5, lane = tid & 31;
    int wy = w >> 1, wx = w & 1;       // warp tile 32M x 32N
    uint32_t sbA = smem_u32(sA), sbB = smem_u32(sB);
    const __nv_bfloat16* Ag = g_qb + (size_t)(h*L_ + i0)*NK;
    const __nv_bfloat16* Bg = g_kb + (size_t)(h*L_ + j0)*NK;
    const int TB = 64*DSTRIDE*2;
    auto issue = [&](int buf, int kofs) {
#pragma unroll
        for (int u = 0; u < 4; u++) {
            int e = tid + 128*u; int row = e >> 3, seg = e & 7;
            cpa16(sbA + buf*TB + (row*DSTRIDE + seg*8)*2, Ag + (size_t)row*NK + kofs + seg*8);
            cpa16(sbB + buf*TB + (row*DSTRIDE + seg*8)*2, Bg + (size_t)row*NK + kofs + seg*8);
        }
        CP_COMMIT();
    };
    issue(0, 0); CP_WAIT0(); __syncthreads();
    float acc[2][4][4] = {};
    for (int kt = 0; kt < 288; kt++) {
        int cur = kt & 1;
        if (kt + 1 < 288) issue(cur ^ 1, (kt+1)*64);
#pragma unroll
        for (int ks = 0; ks < 4; ks++) {
            uint32_t bfr[4][2];
#pragma unroll
            for (int nt = 0; nt < 4; nt++)
                ldsm2(bfr[nt], sbB + cur*TB + ((wx*32 + nt*8 + (lane&7))*DSTRIDE + ks*16 + (lane&8))*2);
#pragma unroll
            for (int mt = 0; mt < 2; mt++) {
                uint32_t af[4];
                ldsm4(af, sbA + cur*TB + ((wy*32 + mt*16 + (lane&15))*DSTRIDE + ks*16 + ((lane>>4)<<3))*2);
#pragma unroll
                for (int nt = 0; nt < 4; nt++)
                    mma16816(acc[mt][nt], af, bfr[nt]);
            }
        }
        if (kt + 1 < 288) CP_WAIT0();
        __syncthreads();
    }
#pragma unroll
    for (int mt = 0; mt < 2; mt++) {
        int r = i0 + wy*32 + mt*16 + (lane>>2);
#pragma unroll
        for (int nt = 0; nt < 4; nt++) {
            int c = j0 + wx*32 + nt*8 + (lane&3)*2;
            size_t base = ((size_t)(h*L_ + r))*L_ + c;
            g_attn[base]   = acc[mt][nt][0] + g_bh[base];
            g_attn[base+1] = acc[mt][nt][1] + g_bh[base+1];
            size_t b8 = base + (size_t)8*L_;
            g_attn[b8]   = acc[mt][nt][2] + g_bh[b8];
            g_attn[b8+1] = acc[mt][nt][3] + g_bh[b8+1];
        }
    }
}

// ---------------- E: softmax over j + post-softmax mask -> hi/lo bf16 ----------------
__global__ void kE(const float* __restrict__ mask) {
    int b = blockIdx.x;               // b = h*L + i
    int i = b - (b / L_) * L_;
    float* row = g_attn + (size_t)b * L_;
    int t = threadIdx.x;              // 128 threads
    float v[3];
    float mx = -1e30f;
#pragma unroll
    for (int u = 0; u < 3; u++) { v[u] = row[t + 128*u]; mx = fmaxf(mx, v[u]); }
    __shared__ float smx[4], ssum[4];
#pragma unroll
    for (int o = 16; o; o >>= 1) mx = fmaxf(mx, __shfl_xor_sync(0xffffffffu, mx, o));
    if ((t & 31) == 0) smx[t >> 5] = mx;
    __syncthreads();
    mx = fmaxf(fmaxf(smx[0], smx[1]), fmaxf(smx[2], smx[3]));
    float s = 0.f;
#pragma unroll
    for (int u = 0; u < 3; u++) { v[u] = expf(v[u] - mx); s += v[u]; }
#pragma unroll
    for (int o = 16; o; o >>= 1) s += __shfl_xor_sync(0xffffffffu, s, o);
    if ((t & 31) == 0) ssum[t >> 5] = s;
    __syncthreads();
    s = ssum[0] + ssum[1] + ssum[2] + ssum[3];
    float inv = 1.f / s;
#pragma unroll
    for (int u = 0; u < 3; u++) {
        int j = t + 128*u;
        float p = v[u]*inv + INF_ * (mask[(size_t)i*L_ + j] - 1.f);
        __nv_bfloat16 hi = __float2bfloat16(p);
        g_ahi[(size_t)b*L_ + j] = hi;
        g_alo[(size_t)b*L_ + j] = __float2bfloat16(p - __bfloat162float(hi));
    }
}

// ---------------- Fm: AV via mma.sync split-bf16, gated, writes ogT ----------------
__global__ void __launch_bounds__(256) kFm() {
    extern __shared__ __align__(16) char dyn[];
    int h = blockIdx.z, i0 = blockIdx.y*128, C0 = blockIdx.x*128;
    int tid = threadIdx.x, w = tid >> 5, lane = tid & 31;
    int wy = w >> 2, wx = w & 3;
    uint32_t sb = smem_u32(dyn);
    const __nv_bfloat16* M0 = g_ahi  + (size_t)(h*L_ + i0)*L_;
    const __nv_bfloat16* M1 = g_alo  + (size_t)(h*L_ + i0)*L_;
    const __nv_bfloat16* M2 = g_vThi + ((size_t)h*NK + C0)*L_;
    const __nv_bfloat16* M3 = g_vTlo + ((size_t)h*NK + C0)*L_;
    const __nv_bfloat16* Ms[4] = {M0, M1, M2, M3};
    float acc[4][4][4] = {};
    auto issue = [&](int buf, int kofs) {
#pragma unroll
        for (int u = 0; u < 8; u++) {
            int e = tid + 256*u;
            int mat = e >> 9, rem = e & 511;
            int row = rem >> 2, seg = rem & 3;
            cpa16(sb + buf*(4*TILEB) + mat*TILEB + (row*TSTRIDE + seg*8)*2,
                  Ms[mat] + (size_t)row*L_ + kofs + seg*8);
        }
        CP_COMMIT();
    };
    issue(0, 0);
    CP_WAIT0();
    __syncthreads();
    for (int kt = 0; kt < 12; kt++) {
        int cur = kt & 1;
        if (kt + 1 < 12) issue(cur ^ 1, (kt+1)*32);
        uint32_t base = sb + cur*(4*TILEB);
#pragma unroll
        for (int ks = 0; ks < 2; ks++) {
            uint32_t bh[4][2], bl[4][2];
#pragma unroll
            for (int nt = 0; nt < 4; nt++) {
                uint32_t ro = ((wx*32 + nt*8 + (lane&7))*TSTRIDE + ks*16 + (lane&8))*2;
                ldsm2(bh[nt], base + 2*TILEB + ro);
                ldsm2(bl[nt], base + 3*TILEB + ro);
            }
#pragma unroll
            for (int mt = 0; mt < 4; mt++) {
                uint32_t ah[4], al[4];
                uint32_t ro = ((wy*64 + mt*16 + (lane&15))*TSTRIDE + ks*16 + ((lane>>4)<<3))*2;
                ldsm4(ah, base + 0*TILEB + ro);
                ldsm4(al, base + 1*TILEB + ro);
#pragma unroll
                for (int nt = 0; nt < 4; nt++) {
                    mma16816(acc[mt][nt], ah, bh[nt]);
                    mma16816(acc[mt][nt], ah, bl[nt]);
                    mma16816(acc[mt][nt], al, bh[nt]);
                }
            }
        }
        if (kt + 1 < 12) CP_WAIT0();
        __syncthreads();
    }
    float* ss = (float*)dyn;
#pragma unroll
    for (int half = 0; half < 2; half++) {
        __syncthreads();
        if ((wx >> 1) == half) {
            int cl0 = (wx & 1)*32;
#pragma unroll
            for (int mt = 0; mt < 4; mt++) {
                int il = wy*64 + mt*16 + (lane>>2);
#pragma unroll
                for (int nt = 0; nt < 4; nt++) {
                    int cl = cl0 + nt*8 + (lane&3)*2;
                    ss[cl*130 + il]       = acc[mt][nt][0];
                    ss[(cl+1)*130 + il]   = acc[mt][nt][1];
                    ss[cl*130 + il+8]     = acc[mt][nt][2];
                    ss[(cl+1)*130 + il+8] = acc[mt][nt][3];
                }
            }
        }
        __syncthreads();
        {
            int cl = tid >> 2, seg = tid & 3;
            int C = C0 + half*64 + cl;
            int n = C / DH, d = C - n*DH;
            size_t gbase = ((size_t)(h*DH + d))*NPAIR + (size_t)n*L_ + i0 + seg*32;
            const float* srow = ss + cl*130 + seg*32;
#pragma unroll
            for (int u = 0; u < 8; u++) {
                float4 o;
                o.x = srow[u*4+0] * g_gateT[gbase + u*4+0];
                o.y = srow[u*4+1] * g_gateT[gbase + u*4+1];
                o.z = srow[u*4+2] * g_gateT[gbase + u*4+2];
                o.w = srow[u*4+3] * g_gateT[gbase + u*4+3];
                *(float4*)(g_ogT + gbase + u*4) = o;
            }
        }
    }
}

// ---------------- G: final projection (reads ogT) + output transpose ----------------
__global__ void kG(const float* __restrict__ Wo, float* __restrict__ out) {
    int r0 = blockIdx.x * 64, c0 = blockIdx.y * 64;
    __shared__ float As[64][65];   // [k][m]
    __shared__ float Bs[64][64];   // [k][n]
    int tx = threadIdx.x, ty = threadIdx.y, tid = ty*16 + tx;
    float acc[4][4] = {};
    for (int kt = 0; kt < 3; kt++) {
        int k0 = kt * 64;
        for (int e = tid; e < 4096; e += 256) {
            int kk = e >> 6, m = e & 63;
            As[kk][m] = g_ogT[(size_t)(k0+kk)*NPAIR + r0 + m];
        }
        for (int e = tid; e < 4096; e += 256) {
            int kk = e >> 6, cn = e & 63;
            Bs[kk][cn] = Wo[(size_t)(k0+kk)*DE + c0 + cn];
        }
        __syncthreads();
#pragma unroll
        for (int kk = 0; kk < 64; kk++) {
            float4 b4 = *(const float4*)&Bs[kk][tx*4];
            float a;
            a = As[kk][ty*4+0]; acc[0][0]+=a*b4.x; acc[0][1]+=a*b4.y; acc[0][2]+=a*b4.z; acc[0][3]+=a*b4.w;
            a = As[kk][ty*4+1]; acc[1][0]+=a*b4.x; acc[1][1]+=a*b4.y; acc[1][2]+=a*b4.z; acc[1][3]+=a*b4.w;
            a = As[kk][ty*4+2]; acc[2][0]+=a*b4.x; acc[2][1]+=a*b4.y; acc[2][2]+=a*b4.z; acc[2][3]+=a*b4.w;
            a = As[kk][ty*4+3]; acc[3][0]+=a*b4.x; acc[3][1]+=a*b4.y; acc[3][2]+=a*b4.z; acc[3][3]+=a*b4.w;
        }
        __syncthreads();
    }
    int n = r0 / L_;
    int ibase = r0 - n * L_;
#pragma unroll
    for (int mi = 0; mi < 4; mi++) {
        int i = ibase + ty*4 + mi;
#pragma unroll
        for (int ni = 0; ni < 4; ni++) {
            out[((size_t)i*L_ + n)*DE + c0 + tx*4 + ni] = acc[mi][ni];
        }
    }
}

// ---------------- launch ----------------
extern "C" void kernel_launch(void* const* d_in, const int* in_sizes, int n_in,
                              void* d_out, int out_size) {
    const float* edge  = (const float*)d_in[0];
    const float* bias  = (const float*)d_in[1];
    const int*   epos  = (const int*)  d_in[2];
    const float* emask = (const float*)d_in[3];
    const float* lneg  = (const float*)d_in[4];
    const float* lneb  = (const float*)d_in[5];
    const float* lnbg  = (const float*)d_in[6];
    const float* lnbb  = (const float*)d_in[7];
    const float* Wq    = (const float*)d_in[8];
    const float* Wk    = (const float*)d_in[9];
    const float* Wv    = (const float*)d_in[10];
    const float* Wb    = (const float*)d_in[11];
    const float* Wg    = (const float*)d_in[12];
    const float* bg    = (const float*)d_in[13];
    const float* Wo    = (const float*)d_in[14];
    float* out = (float*)d_out;

    cudaFuncSetAttribute(kCm, cudaFuncAttributeMaxDynamicSharedMemorySize, 174080);
    cudaFuncSetAttribute(kFm, cudaFuncAttributeMaxDynamicSharedMemorySize, 8*TILEB);

    dim3 b32x8(32, 8);
    kA<<<NPAIR/8, b32x8>>>(edge, lneg, lneb);
    kB<<<NPAIR/8, b32x8>>>(bias, lnbg, lnbb, Wb);
    kRope<<<36, 256>>>(epos);
    kW<<<dim3(HD, 4), DE>>>(Wq, Wk, Wv, Wg);
    kCm<<<NPAIR/128, 256, 174080>>>(bg);
    kTv<<<dim3(3, L_*NH), 256>>>();
    kDm<<<dim3(6, 6, NH), 128>>>();
    kE<<<NH*L_, 128>>>(emask);
    kFm<<<dim3(NK/128, 3, NH), 256, 8*TILEB>>>();
    kG<<<dim3(NPAIR/64, 2), dim3(16,16)>>>(Wo, out);
}

// round 8
// speedup vs baseline: 3.4864x; 1.1374x over previous
#include <cuda_runtime.h>
#include <cuda_bf16.h>
#include <stdint.h>
#include <math.h>

#define L_      384
#define DE      128
#define DB      64
#define NH      4
#define DH      48
#define HD      (NH*DH)        // 192
#define NPAIR   (L_*L_)        // 147456
#define NK      (L_*DH)        // 18432
#define EPS_    1e-5f
#define INF_    1000000.0f
#define SCALE_  0.14433756729740643f   // 1/sqrt(48)

// ---------------- scratch ----------------
__device__ __nv_bfloat16 g_ehi[(size_t)NPAIR*DE];   // LN(edge^T) split
__device__ __nv_bfloat16 g_elo[(size_t)NPAIR*DE];
__device__ __nv_bfloat16 g_wthi[4*HD*DE];           // W^T [mode][n][k] split; mode: 0=q,1=k,2=g,3=v
__device__ __nv_bfloat16 g_wtlo[4*HD*DE];
__device__ __nv_bfloat16 g_wohi[DE*HD];             // Wo^T [o][k] split
__device__ __nv_bfloat16 g_wolo[DE*HD];
__device__ __nv_bfloat16 g_qb[(size_t)NH*L_*NK];    // [h][i][n*48+d] post-RoPE * SCALE
__device__ __nv_bfloat16 g_kb[(size_t)NH*L_*NK];    // post-RoPE / L
__device__ __nv_bfloat16 g_vThi[(size_t)NH*NK*L_];  // [h][n*48+d][j]
__device__ __nv_bfloat16 g_vTlo[(size_t)NH*NK*L_];
__device__ float g_gate[(size_t)NPAIR*HD];          // [r=n*L+i][h*48+d]
__device__ float g_bh  [NH*L_*L_];                  // [h][i][j]
__device__ float g_attn[NH*L_*L_];
__device__ __nv_bfloat16 g_ahi[NH*L_*L_];
__device__ __nv_bfloat16 g_alo[NH*L_*L_];
__device__ __nv_bfloat16 g_oghi[(size_t)NPAIR*HD];  // gated AV out [r][c] split
__device__ __nv_bfloat16 g_oglo[(size_t)NPAIR*HD];
__device__ float g_tc  [L_*24];
__device__ float g_ts  [L_*24];

// ================= warp-MMA helpers =================
__device__ __forceinline__ uint32_t smem_u32(const void* p){
    uint32_t a;
    asm("{ .reg .u64 t; cvta.to.shared.u64 t, %1; cvt.u32.u64 %0, t; }" : "=r"(a) : "l"(p));
    return a;
}
__device__ __forceinline__ void ldsm4(uint32_t* r, uint32_t addr){
    asm volatile("ldmatrix.sync.aligned.m8n8.x4.shared.b16 {%0,%1,%2,%3}, [%4];"
        : "=r"(r[0]),"=r"(r[1]),"=r"(r[2]),"=r"(r[3]) : "r"(addr));
}
__device__ __forceinline__ void ldsm2(uint32_t* r, uint32_t addr){
    asm volatile("ldmatrix.sync.aligned.m8n8.x2.shared.b16 {%0,%1}, [%2];"
        : "=r"(r[0]),"=r"(r[1]) : "r"(addr));
}
__device__ __forceinline__ void mma16816(float* c, const uint32_t* a, const uint32_t* b){
    asm volatile("mma.sync.aligned.m16n8k16.row.col.f32.bf16.bf16.f32 "
        "{%0,%1,%2,%3}, {%4,%5,%6,%7}, {%8,%9}, {%0,%1,%2,%3};"
        : "+f"(c[0]), "+f"(c[1]), "+f"(c[2]), "+f"(c[3])
        : "r"(a[0]), "r"(a[1]), "r"(a[2]), "r"(a[3]), "r"(b[0]), "r"(b[1]));
}
__device__ __forceinline__ void cpa16(uint32_t saddr, const void* g){
    asm volatile("cp.async.cg.shared.global [%0], [%1], 16;" :: "r"(saddr), "l"(g));
}
#define CP_COMMIT() asm volatile("cp.async.commit_group;" ::: "memory")
#define CP_WAIT0()  asm volatile("cp.async.wait_group 0;" ::: "memory")
__device__ __forceinline__ float sigm(float x){ return 1.f/(1.f+expf(-x)); }

#define TSTRIDE 40               // kFm smem row stride (bf16 elems)
#define TILEB   (128*TSTRIDE*2)
#define TS2     136              // kCm row stride (K=128 + pad)
#define DSTRIDE 72               // kDm row stride (K=64 + pad)
#define GSTR    200              // kGm row stride (K=192 + pad)

// ---------------- A: layernorm of transposed edge -> hi/lo bf16 ----------------
__global__ void kA(const float* __restrict__ edge, const float* __restrict__ gg,
                   const float* __restrict__ bb) {
    int row  = blockIdx.x * 8 + threadIdx.y;          // r = n*L + i
    int n    = row / L_;
    int i    = row - n * L_;
    int lane = threadIdx.x;
    const float* x = edge + ((size_t)i * L_ + n) * DE;
    float v[4], s = 0.f, s2 = 0.f;
#pragma unroll
    for (int t = 0; t < 4; t++) {
        float xv = x[lane + 32*t];
        v[t] = xv; s += xv; s2 += xv*xv;
    }
#pragma unroll
    for (int o = 16; o; o >>= 1) {
        s  += __shfl_xor_sync(0xffffffffu, s,  o);
        s2 += __shfl_xor_sync(0xffffffffu, s2, o);
    }
    float mu = s * (1.f/DE);
    float var = s2 * (1.f/DE) - mu*mu;
    float r = rsqrtf(var + EPS_);
#pragma unroll
    for (int t = 0; t < 4; t++) {
        int c = lane + 32*t;
        float yv = (v[t]-mu)*r*gg[c] + bb[c];
        __nv_bfloat16 hi = __float2bfloat16(yv);
        g_ehi[(size_t)row*DE + c] = hi;
        g_elo[(size_t)row*DE + c] = __float2bfloat16(yv - __bfloat162float(hi));
    }
}

// ---------------- B: layernorm of transposed bias + Wb -> b_h[h][i][j] ----------------
__global__ void kB(const float* __restrict__ bias, const float* __restrict__ gg,
                   const float* __restrict__ bb, const float* __restrict__ Wb) {
    int p = blockIdx.x * 8 + threadIdx.y;             // p = i*L + j
    int i = p / L_;
    int j = p - i * L_;
    int lane = threadIdx.x;
    const float* x = bias + ((size_t)j * L_ + i) * DB;
    float x0 = x[lane], x1 = x[lane+32];
    float s = x0 + x1, s2 = x0*x0 + x1*x1;
#pragma unroll
    for (int o = 16; o; o >>= 1) {
        s  += __shfl_xor_sync(0xffffffffu, s,  o);
        s2 += __shfl_xor_sync(0xffffffffu, s2, o);
    }
    float mu = s * (1.f/DB);
    float var = s2 * (1.f/DB) - mu*mu;
    float r = rsqrtf(var + EPS_);
    float y0 = (x0-mu)*r*gg[lane]    + bb[lane];
    float y1 = (x1-mu)*r*gg[lane+32] + bb[lane+32];
    float a[4];
#pragma unroll
    for (int h = 0; h < 4; h++)
        a[h] = y0 * Wb[lane*NH + h] + y1 * Wb[(lane+32)*NH + h];
#pragma unroll
    for (int h = 0; h < 4; h++)
#pragma unroll
        for (int o = 16; o; o >>= 1)
            a[h] += __shfl_xor_sync(0xffffffffu, a[h], o);
    if (lane < 4)
        g_bh[((size_t)lane * L_ + i) * L_ + j] = a[lane];
}

// ---------------- RoPE table ----------------
__global__ void kRope(const int* __restrict__ pos) {
    int t = blockIdx.x * 256 + threadIdx.x;
    if (t >= L_*24) return;
    int i = t / 24, d = t - (t/24)*24;
    float ang = (float)pos[i] * powf(10000.f, -(float)d * (1.f/24.f));
    float sn, cs; sincosf(ang, &sn, &cs);
    g_tc[t] = cs; g_ts[t] = sn;
}

// ---------------- W: transpose+split QKGV weights -> [mode][n][k] ----------------
__global__ void kW(const float* __restrict__ Wq, const float* __restrict__ Wk,
                   const float* __restrict__ Wv, const float* __restrict__ Wg) {
    int mode = blockIdx.y, nn = blockIdx.x, k = threadIdx.x;   // 128 threads
    const float* W = (mode == 0) ? Wq : (mode == 1) ? Wk : (mode == 2) ? Wg : Wv;
    float x = W[(size_t)k*HD + nn];
    __nv_bfloat16 hi = __float2bfloat16(x);
    size_t o = ((size_t)mode*HD + nn)*DE + k;
    g_wthi[o] = hi;
    g_wtlo[o] = __float2bfloat16(x - __bfloat162float(hi));
}

// ---------------- W2: transpose+split Wo -> [o][k] ----------------
__global__ void kW2(const float* __restrict__ Wo) {
    int o = blockIdx.x, k = threadIdx.x;    // 192 threads
    float x = Wo[(size_t)k*DE + o];
    __nv_bfloat16 hi = __float2bfloat16(x);
    g_wohi[(size_t)o*HD + k] = hi;
    g_wolo[(size_t)o*HD + k] = __float2bfloat16(x - __bfloat162float(hi));
}

// ---------------- Cm: QKGV projections via mma.sync split-bf16 ----------------
// mode order: 0=q (RoPE), 1=k (RoPE), 2=gate, 3=v (transposed split write)
__global__ void __launch_bounds__(256) kCm(const float* __restrict__ bg) {
    extern __shared__ __align__(16) char dyn[];
    __nv_bfloat16* sAh = (__nv_bfloat16*)dyn;
    __nv_bfloat16* sAl = sAh + 128*TS2;
    __nv_bfloat16* sBh = sAl + 128*TS2;
    __nv_bfloat16* sBl = sBh + 192*TS2;
    int r0 = blockIdx.x * 128;
    int tid = threadIdx.x, w = tid >> 5, lane = tid & 31;
    int wy = w >> 2, wx = w & 3;     // 2x4 warps; warp tile 64M x 48N; wx == head
    uint32_t aAh = smem_u32(sAh), aAl = smem_u32(sAl);
    uint32_t aBh = smem_u32(sBh), aBl = smem_u32(sBl);
    int n = r0 / L_;
    int ibase = r0 - n * L_;
#pragma unroll
    for (int u = 0; u < 8; u++) {
        int e = tid + 256*u; int row = e >> 4, seg = e & 15;
        cpa16(aAh + (row*TS2 + seg*8)*2, g_ehi + (size_t)(r0+row)*DE + seg*8);
        cpa16(aAl + (row*TS2 + seg*8)*2, g_elo + (size_t)(r0+row)*DE + seg*8);
    }
#pragma unroll
    for (int u = 0; u < 12; u++) {
        int e = tid + 256*u; int row = e >> 4, seg = e & 15;
        cpa16(aBh + (row*TS2 + seg*8)*2, g_wthi + (size_t)row*DE + seg*8);
        cpa16(aBl + (row*TS2 + seg*8)*2, g_wtlo + (size_t)row*DE + seg*8);
    }
    CP_COMMIT(); CP_WAIT0(); __syncthreads();

    for (int mode = 0; mode < 4; mode++) {
        float acc[4][6][4];
#pragma unroll
        for (int a1 = 0; a1 < 4; a1++)
#pragma unroll
            for (int a2 = 0; a2 < 6; a2++)
#pragma unroll
                for (int a3 = 0; a3 < 4; a3++) acc[a1][a2][a3] = 0.f;
#pragma unroll
        for (int ks = 0; ks < 8; ks++) {
            uint32_t bh[6][2], bl[6][2];
#pragma unroll
            for (int nt = 0; nt < 6; nt++) {
                uint32_t ro = ((wx*48 + nt*8 + (lane&7))*TS2 + ks*16 + (lane&8))*2;
                ldsm2(bh[nt], aBh + ro);
                ldsm2(bl[nt], aBl + ro);
            }
#pragma unroll
            for (int mt = 0; mt < 4; mt++) {
                uint32_t ah[4], al[4];
                uint32_t ro = ((wy*64 + mt*16 + (lane&15))*TS2 + ks*16 + ((lane>>4)<<3))*2;
                ldsm4(ah, aAh + ro);
                ldsm4(al, aAl + ro);
#pragma unroll
                for (int nt = 0; nt < 6; nt++) {
                    mma16816(acc[mt][nt], ah, bh[nt]);
                    mma16816(acc[mt][nt], ah, bl[nt]);
                    mma16816(acc[mt][nt], al, bh[nt]);
                }
            }
        }
        __syncthreads();
        if (mode < 3) {   // prefetch next mode's weights (overlaps epilogue)
#pragma unroll
            for (int u = 0; u < 12; u++) {
                int e = tid + 256*u; int row = e >> 4, seg = e & 15;
                cpa16(aBh + (row*TS2 + seg*8)*2, g_wthi + (size_t)((mode+1)*HD + row)*DE + seg*8);
                cpa16(aBl + (row*TS2 + seg*8)*2, g_wtlo + (size_t)((mode+1)*HD + row)*DE + seg*8);
            }
            CP_COMMIT();
        }
        // ---- epilogues ----
        if (mode <= 1) {               // q/k: in-register RoPE + scale -> bf16
            float sc = (mode == 0) ? SCALE_ : (1.f/(float)L_);
            __nv_bfloat16* O = (mode == 0) ? g_qb : g_kb;
#pragma unroll
            for (int mt = 0; mt < 4; mt++) {
                int il0 = wy*64 + mt*16 + (lane>>2);
#pragma unroll
                for (int hf = 0; hf < 2; hf++) {
                    int i = ibase + il0 + hf*8;
                    size_t base = ((size_t)(wx*L_ + i))*NK + (size_t)n*DH;
#pragma unroll
                    for (int nt = 0; nt < 3; nt++) {
                        int d0 = nt*8 + (lane&3)*2;
                        float x1a = acc[mt][nt  ][hf*2+0], x1b = acc[mt][nt  ][hf*2+1];
                        float x2a = acc[mt][nt+3][hf*2+0], x2b = acc[mt][nt+3][hf*2+1];
                        float c0 = g_tc[i*24+d0],   s0 = g_ts[i*24+d0];
                        float c1 = g_tc[i*24+d0+1], s1 = g_ts[i*24+d0+1];
                        __nv_bfloat162 o1, o2;
                        o1.x = __float2bfloat16((x1a*c0 - x2a*s0)*sc);
                        o1.y = __float2bfloat16((x1b*c1 - x2b*s1)*sc);
                        o2.x = __float2bfloat16((x1a*s0 + x2a*c0)*sc);
                        o2.y = __float2bfloat16((x1b*s1 + x2b*c1)*sc);
                        *(__nv_bfloat162*)(O + base + d0)      = o1;
                        *(__nv_bfloat162*)(O + base + d0 + 24) = o2;
                    }
                }
            }
        } else if (mode == 2) {        // gate: sigmoid + bias, [r][c] float2 writes
#pragma unroll
            for (int mt = 0; mt < 4; mt++) {
                int il0 = wy*64 + mt*16 + (lane>>2);
#pragma unroll
                for (int hf = 0; hf < 2; hf++) {
                    int r = r0 + il0 + hf*8;
#pragma unroll
                    for (int nt = 0; nt < 6; nt++) {
                        int c = wx*48 + nt*8 + (lane&3)*2;
                        float2 o;
                        o.x = sigm(acc[mt][nt][hf*2+0] + bg[c]);
                        o.y = sigm(acc[mt][nt][hf*2+1] + bg[c+1]);
                        *(float2*)(g_gate + (size_t)r*HD + c) = o;
                    }
                }
            }
        } else {                       // v (last): stage [c][j] -> vT hi/lo coalesced
            float* ss = (float*)dyn;   // [192][132] fp32 = 101KB (A/B tiles dead now)
#pragma unroll
            for (int mt = 0; mt < 4; mt++) {
                int il = wy*64 + mt*16 + (lane>>2);
#pragma unroll
                for (int nt = 0; nt < 6; nt++) {
                    int c = wx*48 + nt*8 + (lane&3)*2;
                    ss[(c  )*132 + il    ] = acc[mt][nt][0];
                    ss[(c+1)*132 + il    ] = acc[mt][nt][1];
                    ss[(c  )*132 + il + 8] = acc[mt][nt][2];
                    ss[(c+1)*132 + il + 8] = acc[mt][nt][3];
                }
            }
            __syncthreads();
            for (int e = tid; e < 192*128; e += 256) {
                int cl = e >> 7, jj = e & 127;
                int hh = cl / DH, d = cl - hh*DH;
                float x = ss[cl*132 + jj];
                __nv_bfloat16 hi = __float2bfloat16(x);
                size_t o = ((size_t)hh*NK + (size_t)n*DH + d)*L_ + ibase + jj;
                g_vThi[o] = hi;
                g_vTlo[o] = __float2bfloat16(x - __bfloat162float(hi));
            }
        }
        if (mode < 3) { CP_WAIT0(); __syncthreads(); }
    }
}

// ---------------- Dm: logits GEMM 64x64 tiles via mma.sync, + bias ----------------
__global__ void __launch_bounds__(128) kDm() {
    __shared__ __align__(16) __nv_bfloat16 sA[2][64*DSTRIDE];
    __shared__ __align__(16) __nv_bfloat16 sB[2][64*DSTRIDE];
    int h = blockIdx.z, i0 = blockIdx.y*64, j0 = blockIdx.x*64;
    int tid = threadIdx.x, w = tid >> 5, lane = tid & 31;
    int wy = w >> 1, wx = w & 1;       // warp tile 32M x 32N
    uint32_t sbA = smem_u32(sA), sbB = smem_u32(sB);
    const __nv_bfloat16* Ag = g_qb + (size_t)(h*L_ + i0)*NK;
    const __nv_bfloat16* Bg = g_kb + (size_t)(h*L_ + j0)*NK;
    const int TB = 64*DSTRIDE*2;
    auto issue = [&](int buf, int kofs) {
#pragma unroll
        for (int u = 0; u < 4; u++) {
            int e = tid + 128*u; int row = e >> 3, seg = e & 7;
            cpa16(sbA + buf*TB + (row*DSTRIDE + seg*8)*2, Ag + (size_t)row*NK + kofs + seg*8);
            cpa16(sbB + buf*TB + (row*DSTRIDE + seg*8)*2, Bg + (size_t)row*NK + kofs + seg*8);
        }
        CP_COMMIT();
    };
    issue(0, 0); CP_WAIT0(); __syncthreads();
    float acc[2][4][4] = {};
    for (int kt = 0; kt < 288; kt++) {
        int cur = kt & 1;
        if (kt + 1 < 288) issue(cur ^ 1, (kt+1)*64);
#pragma unroll
        for (int ks = 0; ks < 4; ks++) {
            uint32_t bfr[4][2];
#pragma unroll
            for (int nt = 0; nt < 4; nt++)
                ldsm2(bfr[nt], sbB + cur*TB + ((wx*32 + nt*8 + (lane&7))*DSTRIDE + ks*16 + (lane&8))*2);
#pragma unroll
            for (int mt = 0; mt < 2; mt++) {
                uint32_t af[4];
                ldsm4(af, sbA + cur*TB + ((wy*32 + mt*16 + (lane&15))*DSTRIDE + ks*16 + ((lane>>4)<<3))*2);
#pragma unroll
                for (int nt = 0; nt < 4; nt++)
                    mma16816(acc[mt][nt], af, bfr[nt]);
            }
        }
        if (kt + 1 < 288) CP_WAIT0();
        __syncthreads();
    }
#pragma unroll
    for (int mt = 0; mt < 2; mt++) {
        int r = i0 + wy*32 + mt*16 + (lane>>2);
#pragma unroll
        for (int nt = 0; nt < 4; nt++) {
            int c = j0 + wx*32 + nt*8 + (lane&3)*2;
            size_t base = ((size_t)(h*L_ + r))*L_ + c;
            g_attn[base]   = acc[mt][nt][0] + g_bh[base];
            g_attn[base+1] = acc[mt][nt][1] + g_bh[base+1];
            size_t b8 = base + (size_t)8*L_;
            g_attn[b8]   = acc[mt][nt][2] + g_bh[b8];
            g_attn[b8+1] = acc[mt][nt][3] + g_bh[b8+1];
        }
    }
}

// ---------------- E: softmax over j + post-softmax mask -> hi/lo bf16 ----------------
__global__ void kE(const float* __restrict__ mask) {
    int b = blockIdx.x;               // b = h*L + i
    int i = b - (b / L_) * L_;
    float* row = g_attn + (size_t)b * L_;
    int t = threadIdx.x;              // 128 threads
    float v[3];
    float mx = -1e30f;
#pragma unroll
    for (int u = 0; u < 3; u++) { v[u] = row[t + 128*u]; mx = fmaxf(mx, v[u]); }
    __shared__ float smx[4], ssum[4];
#pragma unroll
    for (int o = 16; o; o >>= 1) mx = fmaxf(mx, __shfl_xor_sync(0xffffffffu, mx, o));
    if ((t & 31) == 0) smx[t >> 5] = mx;
    __syncthreads();
    mx = fmaxf(fmaxf(smx[0], smx[1]), fmaxf(smx[2], smx[3]));
    float s = 0.f;
#pragma unroll
    for (int u = 0; u < 3; u++) { v[u] = expf(v[u] - mx); s += v[u]; }
#pragma unroll
    for (int o = 16; o; o >>= 1) s += __shfl_xor_sync(0xffffffffu, s, o);
    if ((t & 31) == 0) ssum[t >> 5] = s;
    __syncthreads();
    s = ssum[0] + ssum[1] + ssum[2] + ssum[3];
    float inv = 1.f / s;
#pragma unroll
    for (int u = 0; u < 3; u++) {
        int j = t + 128*u;
        float p = v[u]*inv + INF_ * (mask[(size_t)i*L_ + j] - 1.f);
        __nv_bfloat16 hi = __float2bfloat16(p);
        g_ahi[(size_t)b*L_ + j] = hi;
        g_alo[(size_t)b*L_ + j] = __float2bfloat16(p - __bfloat162float(hi));
    }
}

// ---------------- Fm: AV via mma.sync split-bf16, gated, writes og [r][c] hi/lo ----------------
__global__ void __launch_bounds__(256) kFm() {
    extern __shared__ __align__(16) char dyn[];
    int h = blockIdx.z, i0 = blockIdx.y*128, C0 = blockIdx.x*128;
    int tid = threadIdx.x, w = tid >> 5, lane = tid & 31;
    int wy = w >> 2, wx = w & 3;
    uint32_t sb = smem_u32(dyn);
    const __nv_bfloat16* M0 = g_ahi  + (size_t)(h*L_ + i0)*L_;
    const __nv_bfloat16* M1 = g_alo  + (size_t)(h*L_ + i0)*L_;
    const __nv_bfloat16* M2 = g_vThi + ((size_t)h*NK + C0)*L_;
    const __nv_bfloat16* M3 = g_vTlo + ((size_t)h*NK + C0)*L_;
    const __nv_bfloat16* Ms[4] = {M0, M1, M2, M3};
    float acc[4][4][4] = {};
    auto issue = [&](int buf, int kofs) {
#pragma unroll
        for (int u = 0; u < 8; u++) {
            int e = tid + 256*u;
            int mat = e >> 9, rem = e & 511;
            int row = rem >> 2, seg = rem & 3;
            cpa16(sb + buf*(4*TILEB) + mat*TILEB + (row*TSTRIDE + seg*8)*2,
                  Ms[mat] + (size_t)row*L_ + kofs + seg*8);
        }
        CP_COMMIT();
    };
    issue(0, 0);
    CP_WAIT0();
    __syncthreads();
    for (int kt = 0; kt < 12; kt++) {
        int cur = kt & 1;
        if (kt + 1 < 12) issue(cur ^ 1, (kt+1)*32);
        uint32_t base = sb + cur*(4*TILEB);
#pragma unroll
        for (int ks = 0; ks < 2; ks++) {
            uint32_t bh[4][2], bl[4][2];
#pragma unroll
            for (int nt = 0; nt < 4; nt++) {
                uint32_t ro = ((wx*32 + nt*8 + (lane&7))*TSTRIDE + ks*16 + (lane&8))*2;
                ldsm2(bh[nt], base + 2*TILEB + ro);
                ldsm2(bl[nt], base + 3*TILEB + ro);
            }
#pragma unroll
            for (int mt = 0; mt < 4; mt++) {
                uint32_t ah[4], al[4];
                uint32_t ro = ((wy*64 + mt*16 + (lane&15))*TSTRIDE + ks*16 + ((lane>>4)<<3))*2;
                ldsm4(ah, base + 0*TILEB + ro);
                ldsm4(al, base + 1*TILEB + ro);
#pragma unroll
                for (int nt = 0; nt < 4; nt++) {
                    mma16816(acc[mt][nt], ah, bh[nt]);
                    mma16816(acc[mt][nt], ah, bl[nt]);
                    mma16816(acc[mt][nt], al, bh[nt]);
                }
            }
        }
        if (kt + 1 < 12) CP_WAIT0();
        __syncthreads();
    }
    float* ss = (float*)dyn;
#pragma unroll
    for (int half = 0; half < 2; half++) {
        __syncthreads();
        if ((wx >> 1) == half) {
            int cl0 = (wx & 1)*32;
#pragma unroll
            for (int mt = 0; mt < 4; mt++) {
                int il = wy*64 + mt*16 + (lane>>2);
#pragma unroll
                for (int nt = 0; nt < 4; nt++) {
                    int cl = cl0 + nt*8 + (lane&3)*2;
                    ss[cl*130 + il]       = acc[mt][nt][0];
                    ss[(cl+1)*130 + il]   = acc[mt][nt][1];
                    ss[cl*130 + il+8]     = acc[mt][nt][2];
                    ss[(cl+1)*130 + il+8] = acc[mt][nt][3];
                }
            }
        }
        __syncthreads();
        for (int e = tid; e < 8192; e += 256) {
            int cl = e & 63, il = e >> 6;
            int C = C0 + half*64 + cl;
            int nn = C / DH, d = C - nn*DH;
            int r = nn*L_ + i0 + il;
            size_t o = (size_t)r*HD + h*DH + d;
            float x = ss[cl*130 + il] * g_gate[o];
            __nv_bfloat16 hi = __float2bfloat16(x);
            g_oghi[o] = hi;
            g_oglo[o] = __float2bfloat16(x - __bfloat162float(hi));
        }
    }
}

// ---------------- Gm: final projection via mma.sync split-bf16 + out transpose ----------------
__global__ void __launch_bounds__(256) kGm(float* __restrict__ out) {
    extern __shared__ __align__(16) char dyn[];
    __nv_bfloat16* sAh = (__nv_bfloat16*)dyn;
    __nv_bfloat16* sAl = sAh + 128*GSTR;
    __nv_bfloat16* sBh = sAl + 128*GSTR;
    __nv_bfloat16* sBl = sBh + 128*GSTR;
    int r0 = blockIdx.x * 128;
    int tid = threadIdx.x, w = tid >> 5, lane = tid & 31;
    int wy = w >> 2, wx = w & 3;     // warp tile 64 rows x 32 out-cols
    uint32_t aAh = smem_u32(sAh), aAl = smem_u32(sAl);
    uint32_t aBh = smem_u32(sBh), aBl = smem_u32(sBl);
#pragma unroll
    for (int u = 0; u < 12; u++) {
        int e = tid + 256*u; int row = e / 24, seg = e % 24;   // 3072 quads per matrix
        cpa16(aAh + (row*GSTR + seg*8)*2, g_oghi + (size_t)(r0+row)*HD + seg*8);
        cpa16(aAl + (row*GSTR + seg*8)*2, g_oglo + (size_t)(r0+row)*HD + seg*8);
        cpa16(aBh + (row*GSTR + seg*8)*2, g_wohi + (size_t)row*HD + seg*8);
        cpa16(aBl + (row*GSTR + seg*8)*2, g_wolo + (size_t)row*HD + seg*8);
    }
    CP_COMMIT(); CP_WAIT0(); __syncthreads();
    float acc[4][4][4] = {};
#pragma unroll
    for (int ks = 0; ks < 12; ks++) {
        uint32_t bh[4][2], bl[4][2];
#pragma unroll
        for (int nt = 0; nt < 4; nt++) {
            uint32_t ro = ((wx*32 + nt*8 + (lane&7))*GSTR + ks*16 + (lane&8))*2;
            ldsm2(bh[nt], aBh + ro);
            ldsm2(bl[nt], aBl + ro);
        }
#pragma unroll
        for (int mt = 0; mt < 4; mt++) {
            uint32_t ah[4], al[4];
            uint32_t ro = ((wy*64 + mt*16 + (lane&15))*GSTR + ks*16 + ((lane>>4)<<3))*2;
            ldsm4(ah, aAh + ro);
            ldsm4(al, aAl + ro);
#pragma unroll
            for (int nt = 0; nt < 4; nt++) {
                mma16816(acc[mt][nt], ah, bh[nt]);
                mma16816(acc[mt][nt], ah, bl[nt]);
                mma16816(acc[mt][nt], al, bh[nt]);
            }
        }
    }
    __syncthreads();
    float* ss = (float*)dyn;          // [128][132] fp32 = 67.6KB
#pragma unroll
    for (int mt = 0; mt < 4; mt++) {
        int il = wy*64 + mt*16 + (lane>>2);
#pragma unroll
        for (int nt = 0; nt < 4; nt++) {
            int o = wx*32 + nt*8 + (lane&3)*2;
            ss[il*132 + o]       = acc[mt][nt][0];
            ss[il*132 + o + 1]   = acc[mt][nt][1];
            ss[(il+8)*132 + o]   = acc[mt][nt][2];
            ss[(il+8)*132 + o+1] = acc[mt][nt][3];
        }
    }
    __syncthreads();
    int n = r0 / L_, ibase = r0 - n*L_;
#pragma unroll
    for (int u = 0; u < 16; u++) {
        int e = tid + 256*u;          // 4096 float4s
        int il = e >> 5, seg = e & 31;
        *(float4*)(out + ((size_t)(ibase+il)*L_ + n)*DE + seg*4) = *(const float4*)(ss + il*132 + seg*4);
    }
}

// ---------------- launch ----------------
extern "C" void kernel_launch(void* const* d_in, const int* in_sizes, int n_in,
                              void* d_out, int out_size) {
    const float* edge  = (const float*)d_in[0];
    const float* bias  = (const float*)d_in[1];
    const int*   epos  = (const int*)  d_in[2];
    const float* emask = (const float*)d_in[3];
    const float* lneg  = (const float*)d_in[4];
    const float* lneb  = (const float*)d_in[5];
    const float* lnbg  = (const float*)d_in[6];
    const float* lnbb  = (const float*)d_in[7];
    const float* Wq    = (const float*)d_in[8];
    const float* Wk    = (const float*)d_in[9];
    const float* Wv    = (const float*)d_in[10];
    const float* Wb    = (const float*)d_in[11];
    const float* Wg    = (const float*)d_in[12];
    const float* bg    = (const float*)d_in[13];
    const float* Wo    = (const float*)d_in[14];
    float* out = (float*)d_out;

    cudaFuncSetAttribute(kCm, cudaFuncAttributeMaxDynamicSharedMemorySize, 174080);
    cudaFuncSetAttribute(kFm, cudaFuncAttributeMaxDynamicSharedMemorySize, 8*TILEB);
    cudaFuncSetAttribute(kGm, cudaFuncAttributeMaxDynamicSharedMemorySize, 204800);

    dim3 b32x8(32, 8);
    kA<<<NPAIR/8, b32x8>>>(edge, lneg, lneb);
    kB<<<NPAIR/8, b32x8>>>(bias, lnbg, lnbb, Wb);
    kRope<<<36, 256>>>(epos);
    kW<<<dim3(HD, 4), DE>>>(Wq, Wk, Wv, Wg);
    kW2<<<DE, HD>>>(Wo);
    kCm<<<NPAIR/128, 256, 174080>>>(bg);
    kDm<<<dim3(6, 6, NH), 128>>>();
    kE<<<NH*L_, 128>>>(emask);
    kFm<<<dim3(NK/128, 3, NH), 256, 8*TILEB>>>();
    kGm<<<NPAIR/128, 256, 204800>>>(out);
}